// round 11
// baseline (speedup 1.0000x reference)
#include <cuda_runtime.h>
#include <cuda_bf16.h>
#include <cuda_fp8.h>
#include <mma.h>
#include <cstdint>

using namespace nvcuda;

#define BB   128
#define TT   17
#define EE   512
#define HH   512
#define VV   32000
#define DD2  1024
#define MM   (BB*TT)     // 2176
#define G4   (4*HH)      // 2048

// big fp8 gemm tiling: 128x64, 3 CTAs/SM
#define MT2  128
#define NT2  64
#define BKB  128
#define KIT  (DD2/BKB)             // 8
#define STG2 (MT2*BKB + NT2*BKB)   // 24576
#define NSTG 3
#define NPART (VV/NT2)             // 500
#define FP8_SCALE 64.0f
#define FP8_INV   (1.0f/4096.0f)

// ---------------- scratch ----------------
__device__ __nv_bfloat16 g_X   [MM*EE];
__device__ float         g_G   [MM*G4];
__device__ __nv_bfloat16 g_h   [BB*HH];
__device__ float         g_c   [BB*HH];
__device__ __nv_bfloat16 g_hs  [MM*HH];
__device__ uint8_t       g_out8[MM*DD2];
__device__ __nv_bfloat16 g_Wih [G4*EE];
__device__ __nv_bfloat16 g_Whh [G4*HH];
__device__ __nv_bfloat16 g_Wd2 [HH*DD2];
__device__ uint8_t       g_W8T [(long)VV*DD2];
__device__ __nv_bfloat16 g_lgt [(long)MM*VV];
__device__ float         g_bsum[G4];
__device__ float         g_rs  [MM];
__device__ float         g_part[(long)MM*NPART];
__device__ unsigned      g_barcnt = 0;
__device__ unsigned      g_gen    = 0;

// ---------------- async copy helpers ----------------
__device__ __forceinline__ void cpa16(void* dst, const void* src) {
    uint32_t d = (uint32_t)__cvta_generic_to_shared(dst);
    asm volatile("cp.async.cg.shared.global [%0], [%1], 16;\n" :: "r"(d), "l"(src));
}
__device__ __forceinline__ void cpa16s(uint32_t d, const void* src) {
    asm volatile("cp.async.cg.shared.global [%0], [%1], 16;\n" :: "r"(d), "l"(src));
}
__device__ __forceinline__ void cpa_commit() { asm volatile("cp.async.commit_group;\n"); }
template<int N> __device__ __forceinline__ void cpa_wait() {
    asm volatile("cp.async.wait_group %0;\n" :: "n"(N));
}
__device__ __forceinline__ uint32_t sw128(uint32_t off) { return off ^ ((off >> 3) & 0x70); }

__device__ __forceinline__ void ldsm_x4(uint32_t& d0, uint32_t& d1, uint32_t& d2, uint32_t& d3,
                                        uint32_t addr) {
    asm volatile("ldmatrix.sync.aligned.m8n8.x4.shared.b16 {%0,%1,%2,%3}, [%4];"
                 : "=r"(d0), "=r"(d1), "=r"(d2), "=r"(d3) : "r"(addr));
}
__device__ __forceinline__ void qmma(float* c, const uint32_t* a, const uint32_t* b) {
    asm volatile("mma.sync.aligned.m16n8k32.row.col.f32.e4m3.e4m3.f32 "
                 "{%0,%1,%2,%3}, {%4,%5,%6,%7}, {%8,%9}, {%0,%1,%2,%3};"
                 : "+f"(c[0]), "+f"(c[1]), "+f"(c[2]), "+f"(c[3])
                 : "r"(a[0]), "r"(a[1]), "r"(a[2]), "r"(a[3]), "r"(b[0]), "r"(b[1]));
}

// ---------------- fused prologue ----------------
#define NB_TR  8000
#define NB_CV  2568
#define NB_FT  256
#define NB_GA  4096
__global__ void __launch_bounds__(256) prep(
    const float* __restrict__ W_last, uint8_t* __restrict__ W8T,
    const float4* __restrict__ Wih_s, __nv_bfloat16* __restrict__ Wih_d,
    const float4* __restrict__ Whh_s, __nv_bfloat16* __restrict__ Whh_d,
    const float4* __restrict__ Wd2_s, __nv_bfloat16* __restrict__ Wd2_d,
    const float* __restrict__ bih, const float* __restrict__ bhh, float* __restrict__ bsum,
    const float* __restrict__ features, const float* __restrict__ W_enc,
    const float* __restrict__ b_enc, const int* __restrict__ captions,
    const float* __restrict__ emb, __nv_bfloat16* __restrict__ X)
{
    __shared__ float tile[128][33];
    int bid = blockIdx.x, tid = threadIdx.x;

    if (bid < NB_TR) {
        int n0 = (bid % 1000) * 32, k0 = (bid / 1000) * 128;
        int tx = tid & 31, ty = tid >> 5;
#pragma unroll
        for (int r = 0; r < 128; r += 8)
            tile[r + ty][tx] = W_last[(long)(k0 + r + ty) * VV + n0 + tx];
        __syncthreads();
#pragma unroll
        for (int nn = 0; nn < 32; nn += 8) {
            int n = n0 + nn + ty;
            uchar4 p;
            p.x = (uint8_t)__nv_cvt_float_to_fp8(tile[tx*4+0][nn+ty] * FP8_SCALE, __NV_SATFINITE, __NV_E4M3);
            p.y = (uint8_t)__nv_cvt_float_to_fp8(tile[tx*4+1][nn+ty] * FP8_SCALE, __NV_SATFINITE, __NV_E4M3);
            p.z = (uint8_t)__nv_cvt_float_to_fp8(tile[tx*4+2][nn+ty] * FP8_SCALE, __NV_SATFINITE, __NV_E4M3);
            p.w = (uint8_t)__nv_cvt_float_to_fp8(tile[tx*4+3][nn+ty] * FP8_SCALE, __NV_SATFINITE, __NV_E4M3);
            *(uchar4*)&W8T[(long)n * DD2 + k0 + tx*4] = p;
        }
        return;
    }
    if (bid < NB_TR + NB_CV) {
        int b2 = bid - NB_TR;
        const float4* src;
        __nv_bfloat16* dst;
        int i;
        if (b2 < 1024)       { src = Wih_s; dst = Wih_d; i = b2*256 + tid; }
        else if (b2 < 2048)  { src = Whh_s; dst = Whh_d; i = (b2-1024)*256 + tid; }
        else if (b2 < 2560)  { src = Wd2_s; dst = Wd2_d; i = (b2-2048)*256 + tid; }
        else {
            int j = (b2-2560)*256 + tid;
            if (j < G4) bsum[j] = bih[j] + bhh[j];
            return;
        }
        float4 v = src[i];
        __nv_bfloat16 t[4];
        t[0] = __float2bfloat16(v.x);
        t[1] = __float2bfloat16(v.y);
        t[2] = __float2bfloat16(v.z);
        t[3] = __float2bfloat16(v.w);
        *(uint2*)&dst[4*i] = *(uint2*)t;
        return;
    }
    if (bid < NB_TR + NB_CV + NB_FT) {
        int b2 = bid - NB_TR - NB_CV;
        int b = b2 >> 1;
        int n = (b2 & 1) * 256 + tid;
        float* fs = &tile[0][0];
        fs[tid]       = features[b*EE + tid];
        fs[tid + 256] = features[b*EE + tid + 256];
        __syncthreads();
        float s = b_enc[n];
#pragma unroll 8
        for (int k = 0; k < EE; k++) s += fs[k] * W_enc[k*EE + n];
        X[(b*TT + 0)*EE + n] = __float2bfloat16(s);
        return;
    }
    int idx = (bid - NB_TR - NB_CV - NB_FT) * 256 + tid;
    int k = idx & (EE-1);
    int r = (idx >> 9) & 15;
    int b = idx >> 13;
    int cap = captions[b*TT + r];
    X[(b*TT + r + 1)*EE + k] = __float2bfloat16(emb[cap*EE + k]);
}

// ---------------- wmma GEMM (G gemm): Cf = A @ B^T + bias ----------------
template<int BM, int BN, int BK, int WM, int WN>
__global__ void __launch_bounds__(256)
gemm2(const __nv_bfloat16* __restrict__ A, const __nv_bfloat16* __restrict__ B,
      int M, int N, int K, const float* __restrict__ bias, float* __restrict__ Cf)
{
    constexpr int BKP = BK + 8;
    constexpr int ASZ = BM * BKP;
    constexpr int BSZ = BN * BKP;
    constexpr int WARPS_N = BN / WN;
    constexpr int FM = WM / 16;
    constexpr int FN = WN / 16;

    extern __shared__ __nv_bfloat16 dynsm[];
    __nv_bfloat16* Asb[2] = { dynsm, dynsm + ASZ };
    __nv_bfloat16* Bsb[2] = { dynsm + 2*ASZ, dynsm + 2*ASZ + BSZ };

    int tid  = threadIdx.x;
    int lane = tid & 31;
    int wid  = tid >> 5;
    int wr   = wid / WARPS_N;
    int wc   = wid % WARPS_N;
    int mBase = blockIdx.x * BM;
    int nBase = blockIdx.y * BN;

    wmma::fragment<wmma::accumulator, 16, 16, 16, float> acc[FM][FN];
#pragma unroll
    for (int i = 0; i < FM; i++)
#pragma unroll
        for (int j = 0; j < FN; j++)
            wmma::fill_fragment(acc[i][j], 0.0f);

    auto loadA = [&](int buf, int k0) {
        constexpr int CPR = BK / 8;
#pragma unroll
        for (int i = 0; i < BM*CPR/256; i++) {
            int cid = tid + i*256;
            int r = cid / CPR, cc = (cid % CPR) * 8;
            cpa16(&Asb[buf][r*BKP + cc], &A[(long)(mBase + r)*K + k0 + cc]);
        }
    };
    auto loadB = [&](int buf, int k0) {
        constexpr int CPR = BK / 8;
#pragma unroll
        for (int i = 0; i < BN*CPR/256; i++) {
            int cid = tid + i*256;
            int r = cid / CPR, cc = (cid % CPR) * 8;
            cpa16(&Bsb[buf][r*BKP + cc], &B[(long)(nBase + r)*K + k0 + cc]);
        }
    };

    loadA(0, 0); loadB(0, 0); cpa_commit();
    int KTn = K / BK;
    for (int kt = 0; kt < KTn; kt++) {
        int buf = kt & 1;
        cpa_wait<0>();
        __syncthreads();
        if (kt + 1 < KTn) { loadA(buf^1, (kt+1)*BK); loadB(buf^1, (kt+1)*BK); cpa_commit(); }
#pragma unroll
        for (int kk = 0; kk < BK; kk += 16) {
            wmma::fragment<wmma::matrix_a, 16, 16, 16, __nv_bfloat16, wmma::row_major> af[FM];
#pragma unroll
            for (int i = 0; i < FM; i++)
                wmma::load_matrix_sync(af[i], &Asb[buf][(wr*WM + i*16)*BKP + kk], BKP);
#pragma unroll
            for (int j = 0; j < FN; j++) {
                wmma::fragment<wmma::matrix_b, 16, 16, 16, __nv_bfloat16, wmma::col_major> bf;
                wmma::load_matrix_sync(bf, &Bsb[buf][(wc*WN + j*16)*BKP + kk], BKP);
#pragma unroll
                for (int i = 0; i < FM; i++)
                    wmma::mma_sync(acc[i][j], af[i], bf, acc[i][j]);
            }
        }
        __syncthreads();
    }

    float* myst = (float*)dynsm + wid * 256;
#pragma unroll
    for (int i = 0; i < FM; i++) {
#pragma unroll
        for (int j = 0; j < FN; j++) {
            wmma::store_matrix_sync(myst, acc[i][j], 16, wmma::mem_row_major);
            __syncwarp();
            int gr0 = mBase + wr*WM + i*16;
            int gc0 = nBase + wc*WN + j*16;
#pragma unroll
            for (int e = lane; e < 256; e += 32) {
                int rr = e >> 4, cc2 = e & 15;
                Cf[(long)(gr0 + rr)*N + (gc0 + cc2)] = myst[e] + bias[gc0 + cc2];
            }
            __syncwarp();
        }
    }
}

// ---------------- persistent LSTM + fused d2 GEMM ----------------
#define PW  520
#define PGP 132
#define D2_AP  72
#define D2_BP  136
__global__ void __launch_bounds__(256) lstm_persist(
    const __nv_bfloat16* __restrict__ Whh, const float* __restrict__ G,
    float* __restrict__ c, __nv_bfloat16* __restrict__ h, __nv_bfloat16* __restrict__ hs,
    const __nv_bfloat16* __restrict__ Wd2, const float* __restrict__ b_d2,
    uint8_t* __restrict__ out8)
{
    extern __shared__ char smraw[];
    __nv_bfloat16* Wsm = (__nv_bfloat16*)smraw;
    __nv_bfloat16* As  = (__nv_bfloat16*)(smraw + 128*PW*2);
    float*         Gst = (float*)(smraw + 128*PW*2 + 16*PW*2);

    int tid = threadIdx.x, lane = tid & 31, wid = tid >> 5;
    int jc0 = (blockIdx.x >> 3) * 32;
    int b0  = (blockIdx.x & 7) * 16;

#pragma unroll
    for (int i = 0; i < 32; i++) {
        int e = tid + i*256;
        int gr = e >> 6, cc = (e & 63) * 8;
        int gate = gr >> 5, r = gr & 31;
        *(uint4*)&Wsm[gr*PW + cc] = *(const uint4*)&Whh[(long)(gate*512 + jc0 + r)*512 + cc];
    }
    __syncthreads();

    auto gridbar = [&]() {
        __threadfence();
        __syncthreads();
        if (tid == 0) {
            unsigned old = *(volatile unsigned*)&g_gen;
            unsigned a = atomicAdd(&g_barcnt, 1);
            if (a == gridDim.x - 1) {
                g_barcnt = 0;
                __threadfence();
                atomicAdd(&g_gen, 1);
            } else {
                while (*(volatile unsigned*)&g_gen == old) { }
            }
        }
        __syncthreads();
        __threadfence();
    };

    for (int t = 0; t < TT; t++) {
        if (t > 0) {
#pragma unroll
            for (int i = 0; i < 4; i++) {
                int e = tid + i*256;
                int r = e >> 6, cc = (e & 63) * 8;
                *(uint4*)&As[r*PW + cc] = __ldcg((const uint4*)&h[(b0 + r)*HH + cc]);
            }
            __syncthreads();

            wmma::fragment<wmma::accumulator, 16, 16, 16, float> acc;
            wmma::fill_fragment(acc, 0.0f);
#pragma unroll 4
            for (int kk = 0; kk < 512; kk += 16) {
                wmma::fragment<wmma::matrix_a, 16, 16, 16, __nv_bfloat16, wmma::row_major> af;
                wmma::load_matrix_sync(af, &As[kk], PW);
                wmma::fragment<wmma::matrix_b, 16, 16, 16, __nv_bfloat16, wmma::col_major> bf;
                wmma::load_matrix_sync(bf, &Wsm[(wid*16)*PW + kk], PW);
                wmma::mma_sync(acc, af, bf, acc);
            }
            wmma::store_matrix_sync(&Gst[wid*16], acc, PGP, wmma::mem_row_major);
            __syncthreads();
        }

#pragma unroll
        for (int i = 0; i < 2; i++) {
            int e = i*256 + tid;
            int jr = e & 31, bl = e >> 5;
            int b = b0 + bl;
            int j = jc0 + jr;
            long grow = (long)(b*TT + t) * G4;
            float s0 = 0.f, s1 = 0.f, s2 = 0.f, s3 = 0.f, cp = 0.f;
            if (t > 0) {
                s0 = Gst[bl*PGP + jr];
                s1 = Gst[bl*PGP + 32 + jr];
                s2 = Gst[bl*PGP + 64 + jr];
                s3 = Gst[bl*PGP + 96 + jr];
                cp = c[b*HH + j];
            }
            float gi = G[grow + j]        + s0;
            float gf = G[grow + 512  + j] + s1;
            float gg = G[grow + 1024 + j] + s2;
            float go = G[grow + 1536 + j] + s3;
            float i_ = 1.f / (1.f + __expf(-gi));
            float f_ = 1.f / (1.f + __expf(-gf));
            float o_ = 1.f / (1.f + __expf(-go));
            float g_ = tanhf(gg);
            float cn = f_*cp + i_*g_;
            float hn = o_*tanhf(cn);
            c[b*HH + j] = cn;
            __nv_bfloat16 hb = __float2bfloat16(hn);
            h[b*HH + j] = hb;
            hs[(long)(b*TT + t)*HH + j] = hb;
        }

        if (t < TT-1) gridbar();
    }

    gridbar();

    // ---------- fused d2 GEMM ----------
    __nv_bfloat16* As2 = (__nv_bfloat16*)smraw;
    __nv_bfloat16* Bs2 = (__nv_bfloat16*)(smraw + 2*128*D2_AP*2);
    float*         est = (float*)(smraw + 2*128*D2_AP*2 + 2*64*D2_BP*2);

    int wr2 = wid >> 1, wc2 = wid & 1;

    for (int tile = blockIdx.x; tile < 136; tile += gridDim.x) {
        int mBase = (tile % 17) * 128;
        int nBase = (tile / 17) * 128;
        __syncthreads();

        wmma::fragment<wmma::accumulator, 16, 16, 16, float> acc[2][4];
#pragma unroll
        for (int i = 0; i < 2; i++)
#pragma unroll
            for (int j = 0; j < 4; j++)
                wmma::fill_fragment(acc[i][j], 0.0f);

        auto loadA2 = [&](int buf, int k0) {
#pragma unroll
            for (int i = 0; i < 4; i++) {
                int cid = tid + i*256;
                int r = cid >> 3, cc = (cid & 7) * 8;
                cpa16(&As2[buf*128*D2_AP + r*D2_AP + cc], &hs[(long)(mBase + r)*HH + k0 + cc]);
            }
        };
        auto loadB2 = [&](int buf, int k0) {
#pragma unroll
            for (int i = 0; i < 4; i++) {
                int cid = tid + i*256;
                int r = cid >> 4, cc = (cid & 15) * 8;
                cpa16(&Bs2[buf*64*D2_BP + r*D2_BP + cc], &Wd2[(long)(k0 + r)*DD2 + nBase + cc]);
            }
        };

        loadA2(0, 0); loadB2(0, 0); cpa_commit();
        for (int kt = 0; kt < 8; kt++) {
            int buf = kt & 1;
            cpa_wait<0>();
            __syncthreads();
            if (kt + 1 < 8) { loadA2(buf^1, (kt+1)*64); loadB2(buf^1, (kt+1)*64); cpa_commit(); }
#pragma unroll
            for (int kk = 0; kk < 64; kk += 16) {
                wmma::fragment<wmma::matrix_a, 16, 16, 16, __nv_bfloat16, wmma::row_major> af[2];
#pragma unroll
                for (int i = 0; i < 2; i++)
                    wmma::load_matrix_sync(af[i], &As2[buf*128*D2_AP + (wr2*32 + i*16)*D2_AP + kk], D2_AP);
#pragma unroll
                for (int j = 0; j < 4; j++) {
                    wmma::fragment<wmma::matrix_b, 16, 16, 16, __nv_bfloat16, wmma::row_major> bf;
                    wmma::load_matrix_sync(bf, &Bs2[buf*64*D2_BP + kk*D2_BP + wc2*64 + j*16], D2_BP);
#pragma unroll
                    for (int i = 0; i < 2; i++)
                        wmma::mma_sync(acc[i][j], af[i], bf, acc[i][j]);
                }
            }
            __syncthreads();
        }

        float* myst = &est[wid * 256];
#pragma unroll
        for (int i = 0; i < 2; i++) {
#pragma unroll
            for (int j = 0; j < 4; j++) {
                wmma::store_matrix_sync(myst, acc[i][j], 16, wmma::mem_row_major);
                __syncwarp();
                int gr0 = mBase + wr2*32 + i*16;
                int gc0 = nBase + wc2*64 + j*16;
#pragma unroll
                for (int e = lane; e < 256; e += 32) {
                    int rr = e >> 4, cc2 = e & 15;
                    out8[(long)(gr0 + rr)*DD2 + (gc0 + cc2)] =
                        (uint8_t)__nv_cvt_float_to_fp8(
                            fmaxf(myst[e] + b_d2[gc0 + cc2], 0.f) * FP8_SCALE,
                            __NV_SATFINITE, __NV_E4M3);
                }
                __syncwarp();
            }
        }
    }
}

// ---------------- big fp8 GEMM: 128x64, 256 thr, 3-stage, 3 CTAs/SM ----------------
__global__ void __launch_bounds__(256, 3) gemm_big8(
    const uint8_t* __restrict__ A8, const uint8_t* __restrict__ B8,
    const float* __restrict__ bias, __nv_bfloat16* __restrict__ lgt, float* __restrict__ part)
{
    extern __shared__ uint8_t sm8[];
    __shared__ float pss[128][2];
    uint32_t sb = (uint32_t)__cvta_generic_to_shared(sm8);

    int tid  = threadIdx.x;
    int lane = tid & 31;
    int wid  = tid >> 5;
    int wr   = wid & 3;           // 0..3 : 32-row slice
    int wc   = wid >> 2;          // 0..1 : 32-col slice
    int mBase = blockIdx.x * MT2;
    int nBase = blockIdx.y * NT2;

    float acc[2][4][4];
#pragma unroll
    for (int f = 0; f < 2; f++)
#pragma unroll
        for (int j = 0; j < 4; j++)
#pragma unroll
            for (int e = 0; e < 4; e++) acc[f][j][e] = 0.f;

    // hoisted load addressing (per-thread invariants)
    const uint8_t* pA = A8 + (long)(mBase + (tid >> 3)) * DD2 + (tid & 7) * 16;
    const uint8_t* pB = B8 + (long)(nBase + (tid >> 3)) * DD2 + (tid & 7) * 16;
    const uint32_t dA = sb + sw128((uint32_t)((tid >> 3) * 128 + (tid & 7) * 16));
    const uint32_t dB = dA + MT2 * BKB;

    auto loadst = [&](int st, int k0) {
        uint32_t ab = dA + st * STG2;
        uint32_t bb = dB + st * STG2;
#pragma unroll
        for (int i = 0; i < 4; i++)                 // A: 128 rows
            cpa16s(ab + i * 4096, pA + k0 + i * 32 * DD2);
#pragma unroll
        for (int i = 0; i < 2; i++)                 // B: 64 rows
            cpa16s(bb + i * 4096, pB + k0 + i * 32 * DD2);
    };

    loadst(0, 0);       cpa_commit();
    loadst(1, BKB);     cpa_commit();

    // precomputed ldsm row offsets with swizzle XOR keys folded out
    int lrow = lane & 15;
    int lcol = (lane & 16) ? 16 : 0;
    uint32_t rowA[2], keyA[2];
#pragma unroll
    for (int f = 0; f < 2; f++) {
        int rr = wr * 32 + f * 16 + lrow;
        rowA[f] = (uint32_t)(rr * 128);
        keyA[f] = (uint32_t)((rr & 7) * 16);
    }
    uint32_t rowB[2], keyB[2];
#pragma unroll
    for (int g = 0; g < 2; g++) {
        int nn = wc * 32 + g * 16 + lrow;
        rowB[g] = (uint32_t)(MT2 * BKB + nn * 128);
        keyB[g] = (uint32_t)((nn & 7) * 16);
    }

    for (int kt = 0; kt < KIT; kt++) {
        int st = kt - (kt / 3) * 3;        // kt % 3
        cpa_wait<1>();
        __syncthreads();
        if (kt + 2 < KIT) {
            int st2 = kt + 2;
            loadst(st2 - (st2 / 3) * 3, st2 * BKB);
        }
        cpa_commit();

        uint32_t stbase = sb + st * STG2;
#pragma unroll
        for (int s = 0; s < 4; s++) {
            uint32_t bytec = (uint32_t)(s * 32 + lcol);
            uint32_t a[2][4];
#pragma unroll
            for (int f = 0; f < 2; f++)
                ldsm_x4(a[f][0], a[f][1], a[f][2], a[f][3],
                        stbase + rowA[f] + (bytec ^ keyA[f]));
            uint32_t b[4][2];
#pragma unroll
            for (int g = 0; g < 2; g++) {
                uint32_t r0, r1, r2, r3;
                ldsm_x4(r0, r1, r2, r3,
                        stbase + rowB[g] + (bytec ^ keyB[g]));
                b[g*2][0] = r0; b[g*2+1][0] = r1;
                b[g*2][1] = r2; b[g*2+1][1] = r3;
            }
#pragma unroll
            for (int f = 0; f < 2; f++)
#pragma unroll
                for (int j = 0; j < 4; j++)
                    qmma(acc[f][j], a[f], b[j]);
        }
    }

    // epilogue: bf16 logits + fused per-row exp partial sums
    float ps[4] = {0.f, 0.f, 0.f, 0.f};
    long rbase = mBase + wr * 32 + (lane >> 2);
#pragma unroll
    for (int f = 0; f < 2; f++) {
        long r0 = rbase + f * 16;
#pragma unroll
        for (int j = 0; j < 4; j++) {
            int col = nBase + wc * 32 + j * 8 + (lane & 3) * 2;
            float2 bv = *(const float2*)&bias[col];
            float l0 = acc[f][j][0] * FP8_INV + bv.x;
            float l1 = acc[f][j][1] * FP8_INV + bv.y;
            float l2 = acc[f][j][2] * FP8_INV + bv.x;
            float l3 = acc[f][j][3] * FP8_INV + bv.y;
            ps[f*2]     += __expf(l0) + __expf(l1);
            ps[f*2 + 1] += __expf(l2) + __expf(l3);
            *(__nv_bfloat162*)&lgt[r0 * VV + col]       = __floats2bfloat162_rn(l0, l1);
            *(__nv_bfloat162*)&lgt[(r0 + 8) * VV + col] = __floats2bfloat162_rn(l2, l3);
        }
    }
#pragma unroll
    for (int k = 0; k < 4; k++) {
        ps[k] += __shfl_xor_sync(0xffffffffu, ps[k], 1);
        ps[k] += __shfl_xor_sync(0xffffffffu, ps[k], 2);
    }
    if ((lane & 3) == 0) {
#pragma unroll
        for (int f = 0; f < 2; f++) {
            pss[wr*32 + f*16 + (lane >> 2)][wc]     = ps[f*2];
            pss[wr*32 + f*16 + 8 + (lane >> 2)][wc] = ps[f*2 + 1];
        }
    }
    __syncthreads();
    if (tid < 128)
        part[(long)(mBase + tid) * NPART + blockIdx.y] = pss[tid][0] + pss[tid][1];
}

// ---------------- softmax: reduce partials, fused exp+normalize ----------------
__global__ void partred_kernel(const float* __restrict__ part, float* __restrict__ rs) {
    __shared__ float red[512];
    int row = blockIdx.x, t = threadIdx.x;
    float s = (t < NPART) ? part[(long)row*NPART + t] : 0.f;
    red[t] = s;
    __syncthreads();
    for (int st = 256; st > 0; st >>= 1) {
        if (t < st) red[t] += red[t + st];
        __syncthreads();
    }
    if (t == 0) rs[row] = 1.f / red[0];
}

__global__ void normexp_kernel(const __nv_bfloat16* __restrict__ lgt,
                               const float* __restrict__ rs, float* __restrict__ out) {
    long idx = (long)blockIdx.x * blockDim.x + threadIdx.x;
    const long tot = (long)MM * VV / 8;
    if (idx >= tot) return;
    int row = (int)((idx * 8) / VV);
    float inv = rs[row];
    uint4 raw = ((const uint4*)lgt)[idx];
    __nv_bfloat162* bp = (__nv_bfloat162*)&raw;
    float4 o0, o1;
    float2 a0 = __bfloat1622float2(bp[0]);
    float2 a1 = __bfloat1622float2(bp[1]);
    float2 a2 = __bfloat1622float2(bp[2]);
    float2 a3 = __bfloat1622float2(bp[3]);
    o0.x = __expf(a0.x) * inv; o0.y = __expf(a0.y) * inv;
    o0.z = __expf(a1.x) * inv; o0.w = __expf(a1.y) * inv;
    o1.x = __expf(a2.x) * inv; o1.y = __expf(a2.y) * inv;
    o1.z = __expf(a3.x) * inv; o1.w = __expf(a3.y) * inv;
    ((float4*)out)[idx*2]     = o0;
    ((float4*)out)[idx*2 + 1] = o1;
}

// ---------------- host launcher ----------------
extern "C" void kernel_launch(void* const* d_in, const int* in_sizes, int n_in,
                              void* d_out, int out_size) {
    const float* features = (const float*)d_in[0];
    const int*   captions = (const int*)  d_in[1];
    const float* W_enc    = (const float*)d_in[2];
    const float* b_enc    = (const float*)d_in[3];
    const float* emb      = (const float*)d_in[4];
    const float* W_ih     = (const float*)d_in[5];
    const float* b_ih     = (const float*)d_in[6];
    const float* W_hh     = (const float*)d_in[7];
    const float* b_hh     = (const float*)d_in[8];
    const float* W_d2     = (const float*)d_in[9];
    const float* b_d2     = (const float*)d_in[10];
    const float* W_last   = (const float*)d_in[11];
    const float* b_last   = (const float*)d_in[12];
    float* out = (float*)d_out;

    void *pX, *pG, *ph, *pc, *phs, *pout8, *pWih, *pWhh, *pWd2, *pW8T, *plgt, *pbsum, *prs, *ppart;
    cudaGetSymbolAddress(&pX, g_X);
    cudaGetSymbolAddress(&pG, g_G);
    cudaGetSymbolAddress(&ph, g_h);
    cudaGetSymbolAddress(&pc, g_c);
    cudaGetSymbolAddress(&phs, g_hs);
    cudaGetSymbolAddress(&pout8, g_out8);
    cudaGetSymbolAddress(&pWih, g_Wih);
    cudaGetSymbolAddress(&pWhh, g_Whh);
    cudaGetSymbolAddress(&pWd2, g_Wd2);
    cudaGetSymbolAddress(&pW8T, g_W8T);
    cudaGetSymbolAddress(&plgt, g_lgt);
    cudaGetSymbolAddress(&pbsum, g_bsum);
    cudaGetSymbolAddress(&prs, g_rs);
    cudaGetSymbolAddress(&ppart, g_part);

    __nv_bfloat16* X     = (__nv_bfloat16*)pX;
    float*         G     = (float*)pG;
    __nv_bfloat16* h     = (__nv_bfloat16*)ph;
    float*         c     = (float*)pc;
    __nv_bfloat16* hs    = (__nv_bfloat16*)phs;
    uint8_t*       out8  = (uint8_t*)pout8;
    __nv_bfloat16* Wih   = (__nv_bfloat16*)pWih;
    __nv_bfloat16* Whh   = (__nv_bfloat16*)pWhh;
    __nv_bfloat16* Wd2   = (__nv_bfloat16*)pWd2;
    uint8_t*       W8T   = (uint8_t*)pW8T;
    __nv_bfloat16* lgt   = (__nv_bfloat16*)plgt;
    float*         bsum  = (float*)pbsum;
    float*         rs    = (float*)prs;
    float*         part  = (float*)ppart;

    const int SMEM_T = 2*(128*40 + 256*40)*2;
    const int SMEM_P = 128*PW*2 + 16*PW*2 + 16*PGP*4;
    const int SMEM_B8 = NSTG * STG2;    // 73728
    cudaFuncSetAttribute(gemm2<128,256,32,64,64>,
                         cudaFuncAttributeMaxDynamicSharedMemorySize, SMEM_T);
    cudaFuncSetAttribute(lstm_persist,
                         cudaFuncAttributeMaxDynamicSharedMemorySize, SMEM_P);
    cudaFuncSetAttribute(gemm_big8,
                         cudaFuncAttributeMaxDynamicSharedMemorySize, SMEM_B8);

    // launch 1: all prologue work fused
    prep<<<NB_TR + NB_CV + NB_FT + NB_GA, 256>>>(
        W_last, W8T,
        (const float4*)W_ih, Wih, (const float4*)W_hh, Whh, (const float4*)W_d2, Wd2,
        b_ih, b_hh, bsum,
        features, W_enc, b_enc, captions, emb, X);

    // launch 2: G = X @ W_ih^T + (b_ih + b_hh)
    gemm2<128,256,32,64,64>
        <<<dim3(MM/128, G4/256), 256, SMEM_T>>>(X, Wih, MM, G4, EE, bsum, G);

    // launch 3: persistent LSTM + fused d2 GEMM -> out8
    lstm_persist<<<128, 256, SMEM_P>>>(Whh, G, c, h, hs, Wd2, b_d2, out8);

    // launch 4: big fp8 GEMM (profiled slot)
    gemm_big8<<<dim3(MM/MT2, VV/NT2), 256, SMEM_B8>>>(out8, W8T, b_last, lgt, part);

    // softmax
    partred_kernel<<<MM, 512>>>(part, rs);
    normexp_kernel<<<(int)(((long)MM*VV/8 + 255)/256), 256>>>(lgt, rs, out);
}

// round 12
// speedup vs baseline: 1.0446x; 1.0446x over previous
#include <cuda_runtime.h>
#include <cuda_bf16.h>
#include <cuda_fp8.h>
#include <mma.h>
#include <cstdint>

using namespace nvcuda;

#define BB   128
#define TT   17
#define EE   512
#define HH   512
#define VV   32000
#define DD2  1024
#define MM   (BB*TT)     // 2176
#define G4   (4*HH)      // 2048

// big fp8 gemm tiling: 128x128, 2 CTAs/SM (R10 config)
#define MT2  128
#define NT2  128
#define BKB  128
#define KIT  (DD2/BKB)             // 8
#define STG2 (MT2*BKB + NT2*BKB)   // 32768
#define NSTG 3
#define NPART (VV/NT2)             // 250
#define FP8_SCALE 64.0f
#define FP8_INV   (1.0f/4096.0f)

// ---------------- scratch ----------------
__device__ __nv_bfloat16 g_X   [MM*EE];
__device__ float         g_G   [MM*G4];
__device__ __nv_bfloat16 g_h   [BB*HH];
__device__ float         g_c   [BB*HH];
__device__ __nv_bfloat16 g_hs  [MM*HH];
__device__ uint8_t       g_out8[MM*DD2];
__device__ __nv_bfloat16 g_Wih [G4*EE];
__device__ __nv_bfloat16 g_Whh [G4*HH];
__device__ __nv_bfloat16 g_Wd2 [HH*DD2];
__device__ uint8_t       g_W8T [(long)VV*DD2];
__device__ __nv_bfloat16 g_lgt [(long)MM*VV];
__device__ float         g_bsum[G4];
__device__ float         g_part[(long)MM*NPART];
__device__ unsigned      g_barcnt = 0;
__device__ unsigned      g_gen    = 0;

// ---------------- async copy helpers ----------------
__device__ __forceinline__ void cpa16(void* dst, const void* src) {
    uint32_t d = (uint32_t)__cvta_generic_to_shared(dst);
    asm volatile("cp.async.cg.shared.global [%0], [%1], 16;\n" :: "r"(d), "l"(src));
}
__device__ __forceinline__ void cpa16s(uint32_t d, const void* src) {
    asm volatile("cp.async.cg.shared.global [%0], [%1], 16;\n" :: "r"(d), "l"(src));
}
__device__ __forceinline__ void cpa_commit() { asm volatile("cp.async.commit_group;\n"); }
template<int N> __device__ __forceinline__ void cpa_wait() {
    asm volatile("cp.async.wait_group %0;\n" :: "n"(N));
}
__device__ __forceinline__ uint32_t sw128(uint32_t off) { return off ^ ((off >> 3) & 0x70); }

__device__ __forceinline__ void ldsm_x4(uint32_t& d0, uint32_t& d1, uint32_t& d2, uint32_t& d3,
                                        uint32_t addr) {
    asm volatile("ldmatrix.sync.aligned.m8n8.x4.shared.b16 {%0,%1,%2,%3}, [%4];"
                 : "=r"(d0), "=r"(d1), "=r"(d2), "=r"(d3) : "r"(addr));
}
__device__ __forceinline__ void qmma(float* c, const uint32_t* a, const uint32_t* b) {
    asm volatile("mma.sync.aligned.m16n8k32.row.col.f32.e4m3.e4m3.f32 "
                 "{%0,%1,%2,%3}, {%4,%5,%6,%7}, {%8,%9}, {%0,%1,%2,%3};"
                 : "+f"(c[0]), "+f"(c[1]), "+f"(c[2]), "+f"(c[3])
                 : "r"(a[0]), "r"(a[1]), "r"(a[2]), "r"(a[3]), "r"(b[0]), "r"(b[1]));
}

// ---------------- fused prologue ----------------
#define NB_TR  8000
#define NB_CV  2568
#define NB_FT  256
#define NB_GA  4096
__global__ void __launch_bounds__(256) prep(
    const float* __restrict__ W_last, uint8_t* __restrict__ W8T,
    const float4* __restrict__ Wih_s, __nv_bfloat16* __restrict__ Wih_d,
    const float4* __restrict__ Whh_s, __nv_bfloat16* __restrict__ Whh_d,
    const float4* __restrict__ Wd2_s, __nv_bfloat16* __restrict__ Wd2_d,
    const float* __restrict__ bih, const float* __restrict__ bhh, float* __restrict__ bsum,
    const float* __restrict__ features, const float* __restrict__ W_enc,
    const float* __restrict__ b_enc, const int* __restrict__ captions,
    const float* __restrict__ emb, __nv_bfloat16* __restrict__ X)
{
    __shared__ float tile[128][33];
    int bid = blockIdx.x, tid = threadIdx.x;

    if (bid < NB_TR) {
        int n0 = (bid % 1000) * 32, k0 = (bid / 1000) * 128;
        int tx = tid & 31, ty = tid >> 5;
#pragma unroll
        for (int r = 0; r < 128; r += 8)
            tile[r + ty][tx] = W_last[(long)(k0 + r + ty) * VV + n0 + tx];
        __syncthreads();
#pragma unroll
        for (int nn = 0; nn < 32; nn += 8) {
            int n = n0 + nn + ty;
            uchar4 p;
            p.x = (uint8_t)__nv_cvt_float_to_fp8(tile[tx*4+0][nn+ty] * FP8_SCALE, __NV_SATFINITE, __NV_E4M3);
            p.y = (uint8_t)__nv_cvt_float_to_fp8(tile[tx*4+1][nn+ty] * FP8_SCALE, __NV_SATFINITE, __NV_E4M3);
            p.z = (uint8_t)__nv_cvt_float_to_fp8(tile[tx*4+2][nn+ty] * FP8_SCALE, __NV_SATFINITE, __NV_E4M3);
            p.w = (uint8_t)__nv_cvt_float_to_fp8(tile[tx*4+3][nn+ty] * FP8_SCALE, __NV_SATFINITE, __NV_E4M3);
            *(uchar4*)&W8T[(long)n * DD2 + k0 + tx*4] = p;
        }
        return;
    }
    if (bid < NB_TR + NB_CV) {
        int b2 = bid - NB_TR;
        const float4* src;
        __nv_bfloat16* dst;
        int i;
        if (b2 < 1024)       { src = Wih_s; dst = Wih_d; i = b2*256 + tid; }
        else if (b2 < 2048)  { src = Whh_s; dst = Whh_d; i = (b2-1024)*256 + tid; }
        else if (b2 < 2560)  { src = Wd2_s; dst = Wd2_d; i = (b2-2048)*256 + tid; }
        else {
            int j = (b2-2560)*256 + tid;
            if (j < G4) bsum[j] = bih[j] + bhh[j];
            return;
        }
        float4 v = src[i];
        __nv_bfloat16 t[4];
        t[0] = __float2bfloat16(v.x);
        t[1] = __float2bfloat16(v.y);
        t[2] = __float2bfloat16(v.z);
        t[3] = __float2bfloat16(v.w);
        *(uint2*)&dst[4*i] = *(uint2*)t;
        return;
    }
    if (bid < NB_TR + NB_CV + NB_FT) {
        int b2 = bid - NB_TR - NB_CV;
        int b = b2 >> 1;
        int n = (b2 & 1) * 256 + tid;
        float* fs = &tile[0][0];
        fs[tid]       = features[b*EE + tid];
        fs[tid + 256] = features[b*EE + tid + 256];
        __syncthreads();
        float s = b_enc[n];
#pragma unroll 8
        for (int k = 0; k < EE; k++) s += fs[k] * W_enc[k*EE + n];
        X[(b*TT + 0)*EE + n] = __float2bfloat16(s);
        return;
    }
    int idx = (bid - NB_TR - NB_CV - NB_FT) * 256 + tid;
    int k = idx & (EE-1);
    int r = (idx >> 9) & 15;
    int b = idx >> 13;
    int cap = captions[b*TT + r];
    X[(b*TT + r + 1)*EE + k] = __float2bfloat16(emb[cap*EE + k]);
}

// ---------------- wmma GEMM (G gemm): Cf = A @ B^T + bias ----------------
template<int BM, int BN, int BK, int WM, int WN>
__global__ void __launch_bounds__(256)
gemm2(const __nv_bfloat16* __restrict__ A, const __nv_bfloat16* __restrict__ B,
      int M, int N, int K, const float* __restrict__ bias, float* __restrict__ Cf)
{
    constexpr int BKP = BK + 8;
    constexpr int ASZ = BM * BKP;
    constexpr int BSZ = BN * BKP;
    constexpr int WARPS_N = BN / WN;
    constexpr int FM = WM / 16;
    constexpr int FN = WN / 16;

    extern __shared__ __nv_bfloat16 dynsm[];
    __nv_bfloat16* Asb[2] = { dynsm, dynsm + ASZ };
    __nv_bfloat16* Bsb[2] = { dynsm + 2*ASZ, dynsm + 2*ASZ + BSZ };

    int tid  = threadIdx.x;
    int lane = tid & 31;
    int wid  = tid >> 5;
    int wr   = wid / WARPS_N;
    int wc   = wid % WARPS_N;
    int mBase = blockIdx.x * BM;
    int nBase = blockIdx.y * BN;

    wmma::fragment<wmma::accumulator, 16, 16, 16, float> acc[FM][FN];
#pragma unroll
    for (int i = 0; i < FM; i++)
#pragma unroll
        for (int j = 0; j < FN; j++)
            wmma::fill_fragment(acc[i][j], 0.0f);

    auto loadA = [&](int buf, int k0) {
        constexpr int CPR = BK / 8;
#pragma unroll
        for (int i = 0; i < BM*CPR/256; i++) {
            int cid = tid + i*256;
            int r = cid / CPR, cc = (cid % CPR) * 8;
            cpa16(&Asb[buf][r*BKP + cc], &A[(long)(mBase + r)*K + k0 + cc]);
        }
    };
    auto loadB = [&](int buf, int k0) {
        constexpr int CPR = BK / 8;
#pragma unroll
        for (int i = 0; i < BN*CPR/256; i++) {
            int cid = tid + i*256;
            int r = cid / CPR, cc = (cid % CPR) * 8;
            cpa16(&Bsb[buf][r*BKP + cc], &B[(long)(nBase + r)*K + k0 + cc]);
        }
    };

    loadA(0, 0); loadB(0, 0); cpa_commit();
    int KTn = K / BK;
    for (int kt = 0; kt < KTn; kt++) {
        int buf = kt & 1;
        cpa_wait<0>();
        __syncthreads();
        if (kt + 1 < KTn) { loadA(buf^1, (kt+1)*BK); loadB(buf^1, (kt+1)*BK); cpa_commit(); }
#pragma unroll
        for (int kk = 0; kk < BK; kk += 16) {
            wmma::fragment<wmma::matrix_a, 16, 16, 16, __nv_bfloat16, wmma::row_major> af[FM];
#pragma unroll
            for (int i = 0; i < FM; i++)
                wmma::load_matrix_sync(af[i], &Asb[buf][(wr*WM + i*16)*BKP + kk], BKP);
#pragma unroll
            for (int j = 0; j < FN; j++) {
                wmma::fragment<wmma::matrix_b, 16, 16, 16, __nv_bfloat16, wmma::col_major> bf;
                wmma::load_matrix_sync(bf, &Bsb[buf][(wc*WN + j*16)*BKP + kk], BKP);
#pragma unroll
                for (int i = 0; i < FM; i++)
                    wmma::mma_sync(acc[i][j], af[i], bf, acc[i][j]);
            }
        }
        __syncthreads();
    }

    float* myst = (float*)dynsm + wid * 256;
#pragma unroll
    for (int i = 0; i < FM; i++) {
#pragma unroll
        for (int j = 0; j < FN; j++) {
            wmma::store_matrix_sync(myst, acc[i][j], 16, wmma::mem_row_major);
            __syncwarp();
            int gr0 = mBase + wr*WM + i*16;
            int gc0 = nBase + wc*WN + j*16;
#pragma unroll
            for (int e = lane; e < 256; e += 32) {
                int rr = e >> 4, cc2 = e & 15;
                Cf[(long)(gr0 + rr)*N + (gc0 + cc2)] = myst[e] + bias[gc0 + cc2];
            }
            __syncwarp();
        }
    }
}

// ---------------- persistent LSTM + fused d2 GEMM ----------------
#define PW  520
#define PGP 132
#define D2_AP  72
#define D2_BP  136
__global__ void __launch_bounds__(256) lstm_persist(
    const __nv_bfloat16* __restrict__ Whh, const float* __restrict__ G,
    float* __restrict__ c, __nv_bfloat16* __restrict__ h, __nv_bfloat16* __restrict__ hs,
    const __nv_bfloat16* __restrict__ Wd2, const float* __restrict__ b_d2,
    uint8_t* __restrict__ out8)
{
    extern __shared__ char smraw[];
    __nv_bfloat16* Wsm = (__nv_bfloat16*)smraw;
    __nv_bfloat16* As  = (__nv_bfloat16*)(smraw + 128*PW*2);
    float*         Gst = (float*)(smraw + 128*PW*2 + 16*PW*2);

    int tid = threadIdx.x, lane = tid & 31, wid = tid >> 5;
    int jc0 = (blockIdx.x >> 3) * 32;
    int b0  = (blockIdx.x & 7) * 16;

#pragma unroll
    for (int i = 0; i < 32; i++) {
        int e = tid + i*256;
        int gr = e >> 6, cc = (e & 63) * 8;
        int gate = gr >> 5, r = gr & 31;
        *(uint4*)&Wsm[gr*PW + cc] = *(const uint4*)&Whh[(long)(gate*512 + jc0 + r)*512 + cc];
    }
    __syncthreads();

    auto gridbar = [&]() {
        __threadfence();
        __syncthreads();
        if (tid == 0) {
            unsigned old = *(volatile unsigned*)&g_gen;
            unsigned a = atomicAdd(&g_barcnt, 1);
            if (a == gridDim.x - 1) {
                g_barcnt = 0;
                __threadfence();
                atomicAdd(&g_gen, 1);
            } else {
                while (*(volatile unsigned*)&g_gen == old) { }
            }
        }
        __syncthreads();
        __threadfence();
    };

    for (int t = 0; t < TT; t++) {
        if (t > 0) {
#pragma unroll
            for (int i = 0; i < 4; i++) {
                int e = tid + i*256;
                int r = e >> 6, cc = (e & 63) * 8;
                *(uint4*)&As[r*PW + cc] = __ldcg((const uint4*)&h[(b0 + r)*HH + cc]);
            }
            __syncthreads();

            wmma::fragment<wmma::accumulator, 16, 16, 16, float> acc;
            wmma::fill_fragment(acc, 0.0f);
#pragma unroll 4
            for (int kk = 0; kk < 512; kk += 16) {
                wmma::fragment<wmma::matrix_a, 16, 16, 16, __nv_bfloat16, wmma::row_major> af;
                wmma::load_matrix_sync(af, &As[kk], PW);
                wmma::fragment<wmma::matrix_b, 16, 16, 16, __nv_bfloat16, wmma::col_major> bf;
                wmma::load_matrix_sync(bf, &Wsm[(wid*16)*PW + kk], PW);
                wmma::mma_sync(acc, af, bf, acc);
            }
            wmma::store_matrix_sync(&Gst[wid*16], acc, PGP, wmma::mem_row_major);
            __syncthreads();
        }

#pragma unroll
        for (int i = 0; i < 2; i++) {
            int e = i*256 + tid;
            int jr = e & 31, bl = e >> 5;
            int b = b0 + bl;
            int j = jc0 + jr;
            long grow = (long)(b*TT + t) * G4;
            float s0 = 0.f, s1 = 0.f, s2 = 0.f, s3 = 0.f, cp = 0.f;
            if (t > 0) {
                s0 = Gst[bl*PGP + jr];
                s1 = Gst[bl*PGP + 32 + jr];
                s2 = Gst[bl*PGP + 64 + jr];
                s3 = Gst[bl*PGP + 96 + jr];
                cp = c[b*HH + j];
            }
            float gi = G[grow + j]        + s0;
            float gf = G[grow + 512  + j] + s1;
            float gg = G[grow + 1024 + j] + s2;
            float go = G[grow + 1536 + j] + s3;
            float i_ = 1.f / (1.f + __expf(-gi));
            float f_ = 1.f / (1.f + __expf(-gf));
            float o_ = 1.f / (1.f + __expf(-go));
            float g_ = tanhf(gg);
            float cn = f_*cp + i_*g_;
            float hn = o_*tanhf(cn);
            c[b*HH + j] = cn;
            __nv_bfloat16 hb = __float2bfloat16(hn);
            h[b*HH + j] = hb;
            hs[(long)(b*TT + t)*HH + j] = hb;
        }

        if (t < TT-1) gridbar();
    }

    gridbar();

    // ---------- fused d2 GEMM ----------
    __nv_bfloat16* As2 = (__nv_bfloat16*)smraw;
    __nv_bfloat16* Bs2 = (__nv_bfloat16*)(smraw + 2*128*D2_AP*2);
    float*         est = (float*)(smraw + 2*128*D2_AP*2 + 2*64*D2_BP*2);

    int wr2 = wid >> 1, wc2 = wid & 1;

    for (int tile = blockIdx.x; tile < 136; tile += gridDim.x) {
        int mBase = (tile % 17) * 128;
        int nBase = (tile / 17) * 128;
        __syncthreads();

        wmma::fragment<wmma::accumulator, 16, 16, 16, float> acc[2][4];
#pragma unroll
        for (int i = 0; i < 2; i++)
#pragma unroll
            for (int j = 0; j < 4; j++)
                wmma::fill_fragment(acc[i][j], 0.0f);

        auto loadA2 = [&](int buf, int k0) {
#pragma unroll
            for (int i = 0; i < 4; i++) {
                int cid = tid + i*256;
                int r = cid >> 3, cc = (cid & 7) * 8;
                cpa16(&As2[buf*128*D2_AP + r*D2_AP + cc], &hs[(long)(mBase + r)*HH + k0 + cc]);
            }
        };
        auto loadB2 = [&](int buf, int k0) {
#pragma unroll
            for (int i = 0; i < 4; i++) {
                int cid = tid + i*256;
                int r = cid >> 4, cc = (cid & 15) * 8;
                cpa16(&Bs2[buf*64*D2_BP + r*D2_BP + cc], &Wd2[(long)(k0 + r)*DD2 + nBase + cc]);
            }
        };

        loadA2(0, 0); loadB2(0, 0); cpa_commit();
        for (int kt = 0; kt < 8; kt++) {
            int buf = kt & 1;
            cpa_wait<0>();
            __syncthreads();
            if (kt + 1 < 8) { loadA2(buf^1, (kt+1)*64); loadB2(buf^1, (kt+1)*64); cpa_commit(); }
#pragma unroll
            for (int kk = 0; kk < 64; kk += 16) {
                wmma::fragment<wmma::matrix_a, 16, 16, 16, __nv_bfloat16, wmma::row_major> af[2];
#pragma unroll
                for (int i = 0; i < 2; i++)
                    wmma::load_matrix_sync(af[i], &As2[buf*128*D2_AP + (wr2*32 + i*16)*D2_AP + kk], D2_AP);
#pragma unroll
                for (int j = 0; j < 4; j++) {
                    wmma::fragment<wmma::matrix_b, 16, 16, 16, __nv_bfloat16, wmma::row_major> bf;
                    wmma::load_matrix_sync(bf, &Bs2[buf*64*D2_BP + kk*D2_BP + wc2*64 + j*16], D2_BP);
#pragma unroll
                    for (int i = 0; i < 2; i++)
                        wmma::mma_sync(acc[i][j], af[i], bf, acc[i][j]);
                }
            }
            __syncthreads();
        }

        float* myst = &est[wid * 256];
#pragma unroll
        for (int i = 0; i < 2; i++) {
#pragma unroll
            for (int j = 0; j < 4; j++) {
                wmma::store_matrix_sync(myst, acc[i][j], 16, wmma::mem_row_major);
                __syncwarp();
                int gr0 = mBase + wr2*32 + i*16;
                int gc0 = nBase + wc2*64 + j*16;
#pragma unroll
                for (int e = lane; e < 256; e += 32) {
                    int rr = e >> 4, cc2 = e & 15;
                    out8[(long)(gr0 + rr)*DD2 + (gc0 + cc2)] =
                        (uint8_t)__nv_cvt_float_to_fp8(
                            fmaxf(myst[e] + b_d2[gc0 + cc2], 0.f) * FP8_SCALE,
                            __NV_SATFINITE, __NV_E4M3);
                }
                __syncwarp();
            }
        }
    }
}

// ---------------- big fp8 GEMM: 128x128, 256 thr, 3-stage, 2 CTAs/SM (R10), unrolled kt ----------------
__global__ void __launch_bounds__(256, 2) gemm_big8(
    const uint8_t* __restrict__ A8, const uint8_t* __restrict__ B8,
    const float* __restrict__ bias, __nv_bfloat16* __restrict__ lgt, float* __restrict__ part)
{
    extern __shared__ uint8_t sm8[];
    __shared__ float pss[128][2];
    uint32_t sb = (uint32_t)__cvta_generic_to_shared(sm8);

    int tid  = threadIdx.x;
    int lane = tid & 31;
    int wid  = tid >> 5;
    int wr   = wid >> 1;          // 0..3 : 32-row slice
    int wc   = wid & 1;           // 0..1 : 64-col slice
    int mBase = blockIdx.x * MT2;
    int nBase = blockIdx.y * NT2;

    float acc[2][8][4];
#pragma unroll
    for (int f = 0; f < 2; f++)
#pragma unroll
        for (int j = 0; j < 8; j++)
#pragma unroll
            for (int e = 0; e < 4; e++) acc[f][j][e] = 0.f;

    // hoisted load addressing
    const uint8_t* pA = A8 + (long)(mBase + (tid >> 3)) * DD2 + (tid & 7) * 16;
    const uint8_t* pB = B8 + (long)(nBase + (tid >> 3)) * DD2 + (tid & 7) * 16;
    const uint32_t dA = sb + sw128((uint32_t)((tid >> 3) * 128 + (tid & 7) * 16));
    const uint32_t dB = dA + MT2 * BKB;

    auto loadst = [&](int st, int k0) {
        uint32_t ab = dA + st * STG2;
        uint32_t bb = dB + st * STG2;
#pragma unroll
        for (int i = 0; i < 4; i++)
            cpa16s(ab + i * 4096, pA + k0 + i * 32 * DD2);
#pragma unroll
        for (int i = 0; i < 4; i++)
            cpa16s(bb + i * 4096, pB + k0 + i * 32 * DD2);
    };

    loadst(0, 0);       cpa_commit();
    loadst(1, BKB);     cpa_commit();

    // precomputed ldsm row offsets with swizzle XOR keys folded out
    int lrow = lane & 15;
    int lcol = (lane & 16) ? 16 : 0;
    uint32_t rowA[2], keyA[2];
#pragma unroll
    for (int f = 0; f < 2; f++) {
        int rr = wr * 32 + f * 16 + lrow;
        rowA[f] = (uint32_t)(rr * 128);
        keyA[f] = (uint32_t)((rr & 7) * 16);
    }
    uint32_t rowB[4], keyB[4];
#pragma unroll
    for (int g = 0; g < 4; g++) {
        int nn = wc * 64 + g * 16 + lrow;
        rowB[g] = (uint32_t)(MT2 * BKB + nn * 128);
        keyB[g] = (uint32_t)((nn & 7) * 16);
    }

#pragma unroll
    for (int kt = 0; kt < KIT; kt++) {
        const int st = kt % 3;             // compile-time after unroll
        cpa_wait<1>();
        __syncthreads();
        if (kt + 2 < KIT) loadst((kt + 2) % 3, (kt + 2) * BKB);
        cpa_commit();

        uint32_t stbase = sb + st * STG2;
#pragma unroll
        for (int s = 0; s < 4; s++) {
            uint32_t bytec = (uint32_t)(s * 32 + lcol);
            uint32_t a[2][4];
#pragma unroll
            for (int f = 0; f < 2; f++)
                ldsm_x4(a[f][0], a[f][1], a[f][2], a[f][3],
                        stbase + rowA[f] + (bytec ^ keyA[f]));
            // B fragments in 2 halves of 4 j-tiles to cap live registers
#pragma unroll
            for (int half = 0; half < 2; half++) {
                uint32_t b[4][2];
#pragma unroll
                for (int g = 0; g < 2; g++) {
                    uint32_t r0, r1, r2, r3;
                    ldsm_x4(r0, r1, r2, r3,
                            stbase + rowB[half*2 + g] + (bytec ^ keyB[half*2 + g]));
                    b[g*2][0] = r0; b[g*2+1][0] = r1;
                    b[g*2][1] = r2; b[g*2+1][1] = r3;
                }
#pragma unroll
                for (int f = 0; f < 2; f++)
#pragma unroll
                    for (int j = 0; j < 4; j++)
                        qmma(acc[f][half*4 + j], a[f], b[j]);
            }
        }
    }

    // epilogue: bf16 logits + fused per-row exp partial sums
    float ps[4] = {0.f, 0.f, 0.f, 0.f};
    long rbase = mBase + wr * 32 + (lane >> 2);
#pragma unroll
    for (int f = 0; f < 2; f++) {
        long r0 = rbase + f * 16;
#pragma unroll
        for (int j = 0; j < 8; j++) {
            int col = nBase + wc * 64 + j * 8 + (lane & 3) * 2;
            float2 bv = *(const float2*)&bias[col];
            float l0 = acc[f][j][0] * FP8_INV + bv.x;
            float l1 = acc[f][j][1] * FP8_INV + bv.y;
            float l2 = acc[f][j][2] * FP8_INV + bv.x;
            float l3 = acc[f][j][3] * FP8_INV + bv.y;
            ps[f*2]     += __expf(l0) + __expf(l1);
            ps[f*2 + 1] += __expf(l2) + __expf(l3);
            *(__nv_bfloat162*)&lgt[r0 * VV + col]       = __floats2bfloat162_rn(l0, l1);
            *(__nv_bfloat162*)&lgt[(r0 + 8) * VV + col] = __floats2bfloat162_rn(l2, l3);
        }
    }
#pragma unroll
    for (int k = 0; k < 4; k++) {
        ps[k] += __shfl_xor_sync(0xffffffffu, ps[k], 1);
        ps[k] += __shfl_xor_sync(0xffffffffu, ps[k], 2);
    }
    if ((lane & 3) == 0) {
#pragma unroll
        for (int f = 0; f < 2; f++) {
            pss[wr*32 + f*16 + (lane >> 2)][wc]     = ps[f*2];
            pss[wr*32 + f*16 + 8 + (lane >> 2)][wc] = ps[f*2 + 1];
        }
    }
    __syncthreads();
    if (tid < 128)
        part[(long)(mBase + tid) * NPART + blockIdx.y] = pss[tid][0] + pss[tid][1];
}

// ---------------- fused softmax: per-row partial reduce + exp + normalize ----------------
// one block per row (MM blocks, 256 threads)
__global__ void __launch_bounds__(256) normexp_row(
    const float* __restrict__ part, const __nv_bfloat16* __restrict__ lgt,
    float* __restrict__ out)
{
    __shared__ float red[256];
    __shared__ float s_inv;
    int row = blockIdx.x, t = threadIdx.x;

    float s = (t < NPART) ? part[(long)row*NPART + t] : 0.f;
    red[t] = s;
    __syncthreads();
#pragma unroll
    for (int st = 128; st > 0; st >>= 1) {
        if (t < st) red[t] += red[t + st];
        __syncthreads();
    }
    if (t == 0) s_inv = 1.f / red[0];
    __syncthreads();
    float inv = s_inv;

    const uint4* lrow = (const uint4*)(lgt + (long)row * VV);
    float4* orow = (float4*)(out + (long)row * VV);
    for (int i = t; i < VV/8; i += 256) {
        uint4 raw = lrow[i];
        __nv_bfloat162* bp = (__nv_bfloat162*)&raw;
        float4 o0, o1;
        float2 a0 = __bfloat1622float2(bp[0]);
        float2 a1 = __bfloat1622float2(bp[1]);
        float2 a2 = __bfloat1622float2(bp[2]);
        float2 a3 = __bfloat1622float2(bp[3]);
        o0.x = __expf(a0.x) * inv; o0.y = __expf(a0.y) * inv;
        o0.z = __expf(a1.x) * inv; o0.w = __expf(a1.y) * inv;
        o1.x = __expf(a2.x) * inv; o1.y = __expf(a2.y) * inv;
        o1.z = __expf(a3.x) * inv; o1.w = __expf(a3.y) * inv;
        orow[i*2]     = o0;
        orow[i*2 + 1] = o1;
    }
}

// ---------------- host launcher ----------------
extern "C" void kernel_launch(void* const* d_in, const int* in_sizes, int n_in,
                              void* d_out, int out_size) {
    const float* features = (const float*)d_in[0];
    const int*   captions = (const int*)  d_in[1];
    const float* W_enc    = (const float*)d_in[2];
    const float* b_enc    = (const float*)d_in[3];
    const float* emb      = (const float*)d_in[4];
    const float* W_ih     = (const float*)d_in[5];
    const float* b_ih     = (const float*)d_in[6];
    const float* W_hh     = (const float*)d_in[7];
    const float* b_hh     = (const float*)d_in[8];
    const float* W_d2     = (const float*)d_in[9];
    const float* b_d2     = (const float*)d_in[10];
    const float* W_last   = (const float*)d_in[11];
    const float* b_last   = (const float*)d_in[12];
    float* out = (float*)d_out;

    void *pX, *pG, *ph, *pc, *phs, *pout8, *pWih, *pWhh, *pWd2, *pW8T, *plgt, *pbsum, *ppart;
    cudaGetSymbolAddress(&pX, g_X);
    cudaGetSymbolAddress(&pG, g_G);
    cudaGetSymbolAddress(&ph, g_h);
    cudaGetSymbolAddress(&pc, g_c);
    cudaGetSymbolAddress(&phs, g_hs);
    cudaGetSymbolAddress(&pout8, g_out8);
    cudaGetSymbolAddress(&pWih, g_Wih);
    cudaGetSymbolAddress(&pWhh, g_Whh);
    cudaGetSymbolAddress(&pWd2, g_Wd2);
    cudaGetSymbolAddress(&pW8T, g_W8T);
    cudaGetSymbolAddress(&plgt, g_lgt);
    cudaGetSymbolAddress(&pbsum, g_bsum);
    cudaGetSymbolAddress(&ppart, g_part);

    __nv_bfloat16* X     = (__nv_bfloat16*)pX;
    float*         G     = (float*)pG;
    __nv_bfloat16* h     = (__nv_bfloat16*)ph;
    float*         c     = (float*)pc;
    __nv_bfloat16* hs    = (__nv_bfloat16*)phs;
    uint8_t*       out8  = (uint8_t*)pout8;
    __nv_bfloat16* Wih   = (__nv_bfloat16*)pWih;
    __nv_bfloat16* Whh   = (__nv_bfloat16*)pWhh;
    __nv_bfloat16* Wd2   = (__nv_bfloat16*)pWd2;
    uint8_t*       W8T   = (uint8_t*)pW8T;
    __nv_bfloat16* lgt   = (__nv_bfloat16*)plgt;
    float*         bsum  = (float*)pbsum;
    float*         part  = (float*)ppart;

    const int SMEM_T = 2*(128*40 + 256*40)*2;
    const int SMEM_P = 128*PW*2 + 16*PW*2 + 16*PGP*4;
    const int SMEM_B8 = NSTG * STG2;    // 98304
    cudaFuncSetAttribute(gemm2<128,256,32,64,64>,
                         cudaFuncAttributeMaxDynamicSharedMemorySize, SMEM_T);
    cudaFuncSetAttribute(lstm_persist,
                         cudaFuncAttributeMaxDynamicSharedMemorySize, SMEM_P);
    cudaFuncSetAttribute(gemm_big8,
                         cudaFuncAttributeMaxDynamicSharedMemorySize, SMEM_B8);

    // launch 1: all prologue work fused
    prep<<<NB_TR + NB_CV + NB_FT + NB_GA, 256>>>(
        W_last, W8T,
        (const float4*)W_ih, Wih, (const float4*)W_hh, Whh, (const float4*)W_d2, Wd2,
        b_ih, b_hh, bsum,
        features, W_enc, b_enc, captions, emb, X);

    // launch 2: G = X @ W_ih^T + (b_ih + b_hh)
    gemm2<128,256,32,64,64>
        <<<dim3(MM/128, G4/256), 256, SMEM_T>>>(X, Wih, MM, G4, EE, bsum, G);

    // launch 3: persistent LSTM + fused d2 GEMM -> out8
    lstm_persist<<<128, 256, SMEM_P>>>(Whh, G, c, h, hs, Wd2, b_d2, out8);

    // launch 4: big fp8 GEMM (profiled slot)
    gemm_big8<<<dim3(MM/MT2, VV/NT2), 256, SMEM_B8>>>(out8, W8T, b_last, lgt, part);

    // launch 5: fused per-row softmax (partial reduce + exp + normalize)
    normexp_row<<<MM, 256>>>(part, lgt, out);
}

// round 13
// speedup vs baseline: 1.0706x; 1.0249x over previous
#include <cuda_runtime.h>
#include <cuda_bf16.h>
#include <cuda_fp8.h>
#include <mma.h>
#include <cstdint>

using namespace nvcuda;

#define BB   128
#define TT   17
#define EE   512
#define HH   512
#define VV   32000
#define DD2  1024
#define MM   (BB*TT)     // 2176
#define G4   (4*HH)      // 2048

// big fp8 gemm tiling: 128x128, 2 CTAs/SM (R10 config)
#define MT2  128
#define NT2  128
#define BKB  128
#define KIT  (DD2/BKB)             // 8
#define STG2 (MT2*BKB + NT2*BKB)   // 32768
#define NSTG 3
#define NPART (VV/NT2)             // 250
#define FP8_SCALE 64.0f
#define FP8_INV   (1.0f/4096.0f)

// ---------------- scratch ----------------
__device__ __nv_bfloat16 g_X   [MM*EE];
__device__ float         g_G   [MM*G4];
__device__ __nv_bfloat16 g_h   [BB*HH];
__device__ float         g_c   [BB*HH];
__device__ __nv_bfloat16 g_hs  [MM*HH];
__device__ uint8_t       g_out8[MM*DD2];
__device__ __nv_bfloat16 g_Wih [G4*EE];
__device__ __nv_bfloat16 g_Whh [G4*HH];
__device__ __nv_bfloat16 g_Wd2 [HH*DD2];
__device__ uint8_t       g_W8T [(long)VV*DD2];
__device__ __nv_bfloat16 g_lgt [(long)MM*VV];
__device__ float         g_bsum[G4];
__device__ float         g_rs  [MM];
__device__ float         g_part[(long)MM*NPART];
__device__ unsigned      g_barcnt = 0;
__device__ unsigned      g_gen    = 0;

// ---------------- async copy helpers ----------------
__device__ __forceinline__ void cpa16(void* dst, const void* src) {
    uint32_t d = (uint32_t)__cvta_generic_to_shared(dst);
    asm volatile("cp.async.cg.shared.global [%0], [%1], 16;\n" :: "r"(d), "l"(src));
}
__device__ __forceinline__ void cpa16s(uint32_t d, const void* src) {
    asm volatile("cp.async.cg.shared.global [%0], [%1], 16;\n" :: "r"(d), "l"(src));
}
__device__ __forceinline__ void cpa_commit() { asm volatile("cp.async.commit_group;\n"); }
template<int N> __device__ __forceinline__ void cpa_wait() {
    asm volatile("cp.async.wait_group %0;\n" :: "n"(N));
}
__device__ __forceinline__ uint32_t sw128(uint32_t off) { return off ^ ((off >> 3) & 0x70); }

__device__ __forceinline__ void ldsm_x4(uint32_t& d0, uint32_t& d1, uint32_t& d2, uint32_t& d3,
                                        uint32_t addr) {
    asm volatile("ldmatrix.sync.aligned.m8n8.x4.shared.b16 {%0,%1,%2,%3}, [%4];"
                 : "=r"(d0), "=r"(d1), "=r"(d2), "=r"(d3) : "r"(addr));
}
__device__ __forceinline__ void qmma(float* c, const uint32_t* a, const uint32_t* b) {
    asm volatile("mma.sync.aligned.m16n8k32.row.col.f32.e4m3.e4m3.f32 "
                 "{%0,%1,%2,%3}, {%4,%5,%6,%7}, {%8,%9}, {%0,%1,%2,%3};"
                 : "+f"(c[0]), "+f"(c[1]), "+f"(c[2]), "+f"(c[3])
                 : "r"(a[0]), "r"(a[1]), "r"(a[2]), "r"(a[3]), "r"(b[0]), "r"(b[1]));
}

// ---------------- W_last transpose -> fp8 (side stream) ----------------
__global__ void __launch_bounds__(256) transpose_f2f8(
    const float* __restrict__ W_last, uint8_t* __restrict__ W8T)
{
    __shared__ float tile[128][33];
    int n0 = blockIdx.x * 32, k0 = blockIdx.y * 128;
    int tx = threadIdx.x & 31, ty = threadIdx.x >> 5;
#pragma unroll
    for (int r = 0; r < 128; r += 8)
        tile[r + ty][tx] = W_last[(long)(k0 + r + ty) * VV + n0 + tx];
    __syncthreads();
#pragma unroll
    for (int nn = 0; nn < 32; nn += 8) {
        int n = n0 + nn + ty;
        uchar4 p;
        p.x = (uint8_t)__nv_cvt_float_to_fp8(tile[tx*4+0][nn+ty] * FP8_SCALE, __NV_SATFINITE, __NV_E4M3);
        p.y = (uint8_t)__nv_cvt_float_to_fp8(tile[tx*4+1][nn+ty] * FP8_SCALE, __NV_SATFINITE, __NV_E4M3);
        p.z = (uint8_t)__nv_cvt_float_to_fp8(tile[tx*4+2][nn+ty] * FP8_SCALE, __NV_SATFINITE, __NV_E4M3);
        p.w = (uint8_t)__nv_cvt_float_to_fp8(tile[tx*4+3][nn+ty] * FP8_SCALE, __NV_SATFINITE, __NV_E4M3);
        *(uchar4*)&W8T[(long)n * DD2 + k0 + tx*4] = p;
    }
}

// ---------------- fused prologue (minus transpose) ----------------
#define NB_CV  2568
#define NB_FT  256
#define NB_GA  4096
__global__ void __launch_bounds__(256) prep_main(
    const float4* __restrict__ Wih_s, __nv_bfloat16* __restrict__ Wih_d,
    const float4* __restrict__ Whh_s, __nv_bfloat16* __restrict__ Whh_d,
    const float4* __restrict__ Wd2_s, __nv_bfloat16* __restrict__ Wd2_d,
    const float* __restrict__ bih, const float* __restrict__ bhh, float* __restrict__ bsum,
    const float* __restrict__ features, const float* __restrict__ W_enc,
    const float* __restrict__ b_enc, const int* __restrict__ captions,
    const float* __restrict__ emb, __nv_bfloat16* __restrict__ X)
{
    __shared__ float fs[EE];
    int bid = blockIdx.x, tid = threadIdx.x;

    if (bid < NB_CV) {
        const float4* src;
        __nv_bfloat16* dst;
        int i;
        if (bid < 1024)       { src = Wih_s; dst = Wih_d; i = bid*256 + tid; }
        else if (bid < 2048)  { src = Whh_s; dst = Whh_d; i = (bid-1024)*256 + tid; }
        else if (bid < 2560)  { src = Wd2_s; dst = Wd2_d; i = (bid-2048)*256 + tid; }
        else {
            int j = (bid-2560)*256 + tid;
            if (j < G4) bsum[j] = bih[j] + bhh[j];
            return;
        }
        float4 v = src[i];
        __nv_bfloat16 t[4];
        t[0] = __float2bfloat16(v.x);
        t[1] = __float2bfloat16(v.y);
        t[2] = __float2bfloat16(v.z);
        t[3] = __float2bfloat16(v.w);
        *(uint2*)&dst[4*i] = *(uint2*)t;
        return;
    }
    if (bid < NB_CV + NB_FT) {
        int b2 = bid - NB_CV;
        int b = b2 >> 1;
        int n = (b2 & 1) * 256 + tid;
        fs[tid]       = features[b*EE + tid];
        fs[tid + 256] = features[b*EE + tid + 256];
        __syncthreads();
        float s = b_enc[n];
#pragma unroll 8
        for (int k = 0; k < EE; k++) s += fs[k] * W_enc[k*EE + n];
        X[(b*TT + 0)*EE + n] = __float2bfloat16(s);
        return;
    }
    int idx = (bid - NB_CV - NB_FT) * 256 + tid;
    int k = idx & (EE-1);
    int r = (idx >> 9) & 15;
    int b = idx >> 13;
    int cap = captions[b*TT + r];
    X[(b*TT + r + 1)*EE + k] = __float2bfloat16(emb[cap*EE + k]);
}

// ---------------- wmma GEMM (G gemm): Cf = A @ B^T + bias ----------------
template<int BM, int BN, int BK, int WM, int WN>
__global__ void __launch_bounds__(256)
gemm2(const __nv_bfloat16* __restrict__ A, const __nv_bfloat16* __restrict__ B,
      int M, int N, int K, const float* __restrict__ bias, float* __restrict__ Cf)
{
    constexpr int BKP = BK + 8;
    constexpr int ASZ = BM * BKP;
    constexpr int BSZ = BN * BKP;
    constexpr int WARPS_N = BN / WN;
    constexpr int FM = WM / 16;
    constexpr int FN = WN / 16;

    extern __shared__ __nv_bfloat16 dynsm[];
    __nv_bfloat16* Asb[2] = { dynsm, dynsm + ASZ };
    __nv_bfloat16* Bsb[2] = { dynsm + 2*ASZ, dynsm + 2*ASZ + BSZ };

    int tid  = threadIdx.x;
    int lane = tid & 31;
    int wid  = tid >> 5;
    int wr   = wid / WARPS_N;
    int wc   = wid % WARPS_N;
    int mBase = blockIdx.x * BM;
    int nBase = blockIdx.y * BN;

    wmma::fragment<wmma::accumulator, 16, 16, 16, float> acc[FM][FN];
#pragma unroll
    for (int i = 0; i < FM; i++)
#pragma unroll
        for (int j = 0; j < FN; j++)
            wmma::fill_fragment(acc[i][j], 0.0f);

    auto loadA = [&](int buf, int k0) {
        constexpr int CPR = BK / 8;
#pragma unroll
        for (int i = 0; i < BM*CPR/256; i++) {
            int cid = tid + i*256;
            int r = cid / CPR, cc = (cid % CPR) * 8;
            cpa16(&Asb[buf][r*BKP + cc], &A[(long)(mBase + r)*K + k0 + cc]);
        }
    };
    auto loadB = [&](int buf, int k0) {
        constexpr int CPR = BK / 8;
#pragma unroll
        for (int i = 0; i < BN*CPR/256; i++) {
            int cid = tid + i*256;
            int r = cid / CPR, cc = (cid % CPR) * 8;
            cpa16(&Bsb[buf][r*BKP + cc], &B[(long)(nBase + r)*K + k0 + cc]);
        }
    };

    loadA(0, 0); loadB(0, 0); cpa_commit();
    int KTn = K / BK;
    for (int kt = 0; kt < KTn; kt++) {
        int buf = kt & 1;
        cpa_wait<0>();
        __syncthreads();
        if (kt + 1 < KTn) { loadA(buf^1, (kt+1)*BK); loadB(buf^1, (kt+1)*BK); cpa_commit(); }
#pragma unroll
        for (int kk = 0; kk < BK; kk += 16) {
            wmma::fragment<wmma::matrix_a, 16, 16, 16, __nv_bfloat16, wmma::row_major> af[FM];
#pragma unroll
            for (int i = 0; i < FM; i++)
                wmma::load_matrix_sync(af[i], &Asb[buf][(wr*WM + i*16)*BKP + kk], BKP);
#pragma unroll
            for (int j = 0; j < FN; j++) {
                wmma::fragment<wmma::matrix_b, 16, 16, 16, __nv_bfloat16, wmma::col_major> bf;
                wmma::load_matrix_sync(bf, &Bsb[buf][(wc*WN + j*16)*BKP + kk], BKP);
#pragma unroll
                for (int i = 0; i < FM; i++)
                    wmma::mma_sync(acc[i][j], af[i], bf, acc[i][j]);
            }
        }
        __syncthreads();
    }

    float* myst = (float*)dynsm + wid * 256;
#pragma unroll
    for (int i = 0; i < FM; i++) {
#pragma unroll
        for (int j = 0; j < FN; j++) {
            wmma::store_matrix_sync(myst, acc[i][j], 16, wmma::mem_row_major);
            __syncwarp();
            int gr0 = mBase + wr*WM + i*16;
            int gc0 = nBase + wc*WN + j*16;
#pragma unroll
            for (int e = lane; e < 256; e += 32) {
                int rr = e >> 4, cc2 = e & 15;
                Cf[(long)(gr0 + rr)*N + (gc0 + cc2)] = myst[e] + bias[gc0 + cc2];
            }
            __syncwarp();
        }
    }
}

// ---------------- persistent LSTM + fused d2 GEMM ----------------
#define PW  520
#define PGP 132
#define D2_AP  72
#define D2_BP  136
__global__ void __launch_bounds__(256) lstm_persist(
    const __nv_bfloat16* __restrict__ Whh, const float* __restrict__ G,
    float* __restrict__ c, __nv_bfloat16* __restrict__ h, __nv_bfloat16* __restrict__ hs,
    const __nv_bfloat16* __restrict__ Wd2, const float* __restrict__ b_d2,
    uint8_t* __restrict__ out8)
{
    extern __shared__ char smraw[];
    __nv_bfloat16* Wsm = (__nv_bfloat16*)smraw;
    __nv_bfloat16* As  = (__nv_bfloat16*)(smraw + 128*PW*2);
    float*         Gst = (float*)(smraw + 128*PW*2 + 16*PW*2);

    int tid = threadIdx.x, lane = tid & 31, wid = tid >> 5;
    int jc0 = (blockIdx.x >> 3) * 32;
    int b0  = (blockIdx.x & 7) * 16;

#pragma unroll
    for (int i = 0; i < 32; i++) {
        int e = tid + i*256;
        int gr = e >> 6, cc = (e & 63) * 8;
        int gate = gr >> 5, r = gr & 31;
        *(uint4*)&Wsm[gr*PW + cc] = *(const uint4*)&Whh[(long)(gate*512 + jc0 + r)*512 + cc];
    }
    __syncthreads();

    auto gridbar = [&]() {
        __threadfence();
        __syncthreads();
        if (tid == 0) {
            unsigned old = *(volatile unsigned*)&g_gen;
            unsigned a = atomicAdd(&g_barcnt, 1);
            if (a == gridDim.x - 1) {
                g_barcnt = 0;
                __threadfence();
                atomicAdd(&g_gen, 1);
            } else {
                while (*(volatile unsigned*)&g_gen == old) { }
            }
        }
        __syncthreads();
        __threadfence();
    };

    for (int t = 0; t < TT; t++) {
        if (t > 0) {
#pragma unroll
            for (int i = 0; i < 4; i++) {
                int e = tid + i*256;
                int r = e >> 6, cc = (e & 63) * 8;
                *(uint4*)&As[r*PW + cc] = __ldcg((const uint4*)&h[(b0 + r)*HH + cc]);
            }
            __syncthreads();

            wmma::fragment<wmma::accumulator, 16, 16, 16, float> acc;
            wmma::fill_fragment(acc, 0.0f);
#pragma unroll 4
            for (int kk = 0; kk < 512; kk += 16) {
                wmma::fragment<wmma::matrix_a, 16, 16, 16, __nv_bfloat16, wmma::row_major> af;
                wmma::load_matrix_sync(af, &As[kk], PW);
                wmma::fragment<wmma::matrix_b, 16, 16, 16, __nv_bfloat16, wmma::col_major> bf;
                wmma::load_matrix_sync(bf, &Wsm[(wid*16)*PW + kk], PW);
                wmma::mma_sync(acc, af, bf, acc);
            }
            wmma::store_matrix_sync(&Gst[wid*16], acc, PGP, wmma::mem_row_major);
            __syncthreads();
        }

#pragma unroll
        for (int i = 0; i < 2; i++) {
            int e = i*256 + tid;
            int jr = e & 31, bl = e >> 5;
            int b = b0 + bl;
            int j = jc0 + jr;
            long grow = (long)(b*TT + t) * G4;
            float s0 = 0.f, s1 = 0.f, s2 = 0.f, s3 = 0.f, cp = 0.f;
            if (t > 0) {
                s0 = Gst[bl*PGP + jr];
                s1 = Gst[bl*PGP + 32 + jr];
                s2 = Gst[bl*PGP + 64 + jr];
                s3 = Gst[bl*PGP + 96 + jr];
                cp = c[b*HH + j];
            }
            float gi = G[grow + j]        + s0;
            float gf = G[grow + 512  + j] + s1;
            float gg = G[grow + 1024 + j] + s2;
            float go = G[grow + 1536 + j] + s3;
            float i_ = 1.f / (1.f + __expf(-gi));
            float f_ = 1.f / (1.f + __expf(-gf));
            float o_ = 1.f / (1.f + __expf(-go));
            float g_ = tanhf(gg);
            float cn = f_*cp + i_*g_;
            float hn = o_*tanhf(cn);
            c[b*HH + j] = cn;
            __nv_bfloat16 hb = __float2bfloat16(hn);
            h[b*HH + j] = hb;
            hs[(long)(b*TT + t)*HH + j] = hb;
        }

        if (t < TT-1) gridbar();
    }

    gridbar();

    // ---------- fused d2 GEMM ----------
    __nv_bfloat16* As2 = (__nv_bfloat16*)smraw;
    __nv_bfloat16* Bs2 = (__nv_bfloat16*)(smraw + 2*128*D2_AP*2);
    float*         est = (float*)(smraw + 2*128*D2_AP*2 + 2*64*D2_BP*2);

    int wr2 = wid >> 1, wc2 = wid & 1;

    for (int tile = blockIdx.x; tile < 136; tile += gridDim.x) {
        int mBase = (tile % 17) * 128;
        int nBase = (tile / 17) * 128;
        __syncthreads();

        wmma::fragment<wmma::accumulator, 16, 16, 16, float> acc[2][4];
#pragma unroll
        for (int i = 0; i < 2; i++)
#pragma unroll
            for (int j = 0; j < 4; j++)
                wmma::fill_fragment(acc[i][j], 0.0f);

        auto loadA2 = [&](int buf, int k0) {
#pragma unroll
            for (int i = 0; i < 4; i++) {
                int cid = tid + i*256;
                int r = cid >> 3, cc = (cid & 7) * 8;
                cpa16(&As2[buf*128*D2_AP + r*D2_AP + cc], &hs[(long)(mBase + r)*HH + k0 + cc]);
            }
        };
        auto loadB2 = [&](int buf, int k0) {
#pragma unroll
            for (int i = 0; i < 4; i++) {
                int cid = tid + i*256;
                int r = cid >> 4, cc = (cid & 15) * 8;
                cpa16(&Bs2[buf*64*D2_BP + r*D2_BP + cc], &Wd2[(long)(k0 + r)*DD2 + nBase + cc]);
            }
        };

        loadA2(0, 0); loadB2(0, 0); cpa_commit();
        for (int kt = 0; kt < 8; kt++) {
            int buf = kt & 1;
            cpa_wait<0>();
            __syncthreads();
            if (kt + 1 < 8) { loadA2(buf^1, (kt+1)*64); loadB2(buf^1, (kt+1)*64); cpa_commit(); }
#pragma unroll
            for (int kk = 0; kk < 64; kk += 16) {
                wmma::fragment<wmma::matrix_a, 16, 16, 16, __nv_bfloat16, wmma::row_major> af[2];
#pragma unroll
                for (int i = 0; i < 2; i++)
                    wmma::load_matrix_sync(af[i], &As2[buf*128*D2_AP + (wr2*32 + i*16)*D2_AP + kk], D2_AP);
#pragma unroll
                for (int j = 0; j < 4; j++) {
                    wmma::fragment<wmma::matrix_b, 16, 16, 16, __nv_bfloat16, wmma::row_major> bf;
                    wmma::load_matrix_sync(bf, &Bs2[buf*64*D2_BP + kk*D2_BP + wc2*64 + j*16], D2_BP);
#pragma unroll
                    for (int i = 0; i < 2; i++)
                        wmma::mma_sync(acc[i][j], af[i], bf, acc[i][j]);
                }
            }
            __syncthreads();
        }

        float* myst = &est[wid * 256];
#pragma unroll
        for (int i = 0; i < 2; i++) {
#pragma unroll
            for (int j = 0; j < 4; j++) {
                wmma::store_matrix_sync(myst, acc[i][j], 16, wmma::mem_row_major);
                __syncwarp();
                int gr0 = mBase + wr2*32 + i*16;
                int gc0 = nBase + wc2*64 + j*16;
#pragma unroll
                for (int e = lane; e < 256; e += 32) {
                    int rr = e >> 4, cc2 = e & 15;
                    out8[(long)(gr0 + rr)*DD2 + (gc0 + cc2)] =
                        (uint8_t)__nv_cvt_float_to_fp8(
                            fmaxf(myst[e] + b_d2[gc0 + cc2], 0.f) * FP8_SCALE,
                            __NV_SATFINITE, __NV_E4M3);
                }
                __syncwarp();
            }
        }
    }
}

// ---------------- big fp8 GEMM: 128x128, 256 thr, 3-stage, 2 CTAs/SM (R10 exact) ----------------
__global__ void __launch_bounds__(256, 2) gemm_big8(
    const uint8_t* __restrict__ A8, const uint8_t* __restrict__ B8,
    const float* __restrict__ bias, __nv_bfloat16* __restrict__ lgt, float* __restrict__ part)
{
    extern __shared__ uint8_t sm8[];
    __shared__ float pss[128][2];
    uint32_t sb = (uint32_t)__cvta_generic_to_shared(sm8);

    int tid  = threadIdx.x;
    int lane = tid & 31;
    int wid  = tid >> 5;
    int wr   = wid >> 1;
    int wc   = wid & 1;
    int mBase = blockIdx.x * MT2;
    int nBase = blockIdx.y * NT2;

    float acc[2][8][4];
#pragma unroll
    for (int f = 0; f < 2; f++)
#pragma unroll
        for (int j = 0; j < 8; j++)
#pragma unroll
            for (int e = 0; e < 4; e++) acc[f][j][e] = 0.f;

    const uint8_t* pA = A8 + (long)(mBase + (tid >> 3)) * DD2 + (tid & 7) * 16;
    const uint8_t* pB = B8 + (long)(nBase + (tid >> 3)) * DD2 + (tid & 7) * 16;
    const uint32_t dA = sb + sw128((uint32_t)((tid >> 3) * 128 + (tid & 7) * 16));
    const uint32_t dB = dA + MT2 * BKB;

    auto loadst = [&](int st, int k0) {
        uint32_t ab = dA + st * STG2;
        uint32_t bb = dB + st * STG2;
#pragma unroll
        for (int i = 0; i < 4; i++)
            cpa16s(ab + i * 4096, pA + k0 + i * 32 * DD2);
#pragma unroll
        for (int i = 0; i < 4; i++)
            cpa16s(bb + i * 4096, pB + k0 + i * 32 * DD2);
    };

    loadst(0, 0);       cpa_commit();
    loadst(1, BKB);     cpa_commit();

    int lrow = lane & 15;
    int lcol = (lane & 16) ? 16 : 0;
    uint32_t rowA[2], keyA[2];
#pragma unroll
    for (int f = 0; f < 2; f++) {
        int rr = wr * 32 + f * 16 + lrow;
        rowA[f] = (uint32_t)(rr * 128);
        keyA[f] = (uint32_t)((rr & 7) * 16);
    }
    uint32_t rowB[4], keyB[4];
#pragma unroll
    for (int g = 0; g < 4; g++) {
        int nn = wc * 64 + g * 16 + lrow;
        rowB[g] = (uint32_t)(MT2 * BKB + nn * 128);
        keyB[g] = (uint32_t)((nn & 7) * 16);
    }

    for (int kt = 0; kt < KIT; kt++) {
        int st = kt - (kt / 3) * 3;
        cpa_wait<1>();
        __syncthreads();
        if (kt + 2 < KIT) {
            int st2 = kt + 2;
            loadst(st2 - (st2 / 3) * 3, st2 * BKB);
        }
        cpa_commit();

        uint32_t stbase = sb + st * STG2;
#pragma unroll
        for (int s = 0; s < 4; s++) {
            uint32_t bytec = (uint32_t)(s * 32 + lcol);
            uint32_t a[2][4];
#pragma unroll
            for (int f = 0; f < 2; f++)
                ldsm_x4(a[f][0], a[f][1], a[f][2], a[f][3],
                        stbase + rowA[f] + (bytec ^ keyA[f]));
#pragma unroll
            for (int half = 0; half < 2; half++) {
                uint32_t b[4][2];
#pragma unroll
                for (int g = 0; g < 2; g++) {
                    uint32_t r0, r1, r2, r3;
                    ldsm_x4(r0, r1, r2, r3,
                            stbase + rowB[half*2 + g] + (bytec ^ keyB[half*2 + g]));
                    b[g*2][0] = r0; b[g*2+1][0] = r1;
                    b[g*2][1] = r2; b[g*2+1][1] = r3;
                }
#pragma unroll
                for (int f = 0; f < 2; f++)
#pragma unroll
                    for (int j = 0; j < 4; j++)
                        qmma(acc[f][half*4 + j], a[f], b[j]);
            }
        }
    }

    float ps[4] = {0.f, 0.f, 0.f, 0.f};
    long rbase = mBase + wr * 32 + (lane >> 2);
#pragma unroll
    for (int f = 0; f < 2; f++) {
        long r0 = rbase + f * 16;
#pragma unroll
        for (int j = 0; j < 8; j++) {
            int col = nBase + wc * 64 + j * 8 + (lane & 3) * 2;
            float2 bv = *(const float2*)&bias[col];
            float l0 = acc[f][j][0] * FP8_INV + bv.x;
            float l1 = acc[f][j][1] * FP8_INV + bv.y;
            float l2 = acc[f][j][2] * FP8_INV + bv.x;
            float l3 = acc[f][j][3] * FP8_INV + bv.y;
            ps[f*2]     += __expf(l0) + __expf(l1);
            ps[f*2 + 1] += __expf(l2) + __expf(l3);
            *(__nv_bfloat162*)&lgt[r0 * VV + col]       = __floats2bfloat162_rn(l0, l1);
            *(__nv_bfloat162*)&lgt[(r0 + 8) * VV + col] = __floats2bfloat162_rn(l2, l3);
        }
    }
#pragma unroll
    for (int k = 0; k < 4; k++) {
        ps[k] += __shfl_xor_sync(0xffffffffu, ps[k], 1);
        ps[k] += __shfl_xor_sync(0xffffffffu, ps[k], 2);
    }
    if ((lane & 3) == 0) {
#pragma unroll
        for (int f = 0; f < 2; f++) {
            pss[wr*32 + f*16 + (lane >> 2)][wc]     = ps[f*2];
            pss[wr*32 + f*16 + 8 + (lane >> 2)][wc] = ps[f*2 + 1];
        }
    }
    __syncthreads();
    if (tid < 128)
        part[(long)(mBase + tid) * NPART + blockIdx.y] = pss[tid][0] + pss[tid][1];
}

// ---------------- softmax: reduce partials, grid-stride exp+normalize (R10 form) ----------------
__global__ void partred_kernel(const float* __restrict__ part, float* __restrict__ rs) {
    __shared__ float red[256];
    int row = blockIdx.x, t = threadIdx.x;
    float s = (t < NPART) ? part[(long)row*NPART + t] : 0.f;
    red[t] = s;
    __syncthreads();
    for (int st = 128; st > 0; st >>= 1) {
        if (t < st) red[t] += red[t + st];
        __syncthreads();
    }
    if (t == 0) rs[row] = 1.f / red[0];
}

__global__ void normexp_kernel(const __nv_bfloat16* __restrict__ lgt,
                               const float* __restrict__ rs, float* __restrict__ out) {
    long idx = (long)blockIdx.x * blockDim.x + threadIdx.x;
    const long tot = (long)MM * VV / 8;
    if (idx >= tot) return;
    int row = (int)((idx * 8) / VV);
    float inv = rs[row];
    uint4 raw = ((const uint4*)lgt)[idx];
    __nv_bfloat162* bp = (__nv_bfloat162*)&raw;
    float4 o0, o1;
    float2 a0 = __bfloat1622float2(bp[0]);
    float2 a1 = __bfloat1622float2(bp[1]);
    float2 a2 = __bfloat1622float2(bp[2]);
    float2 a3 = __bfloat1622float2(bp[3]);
    o0.x = __expf(a0.x) * inv; o0.y = __expf(a0.y) * inv;
    o0.z = __expf(a1.x) * inv; o0.w = __expf(a1.y) * inv;
    o1.x = __expf(a2.x) * inv; o1.y = __expf(a2.y) * inv;
    o1.z = __expf(a3.x) * inv; o1.w = __expf(a3.y) * inv;
    ((float4*)out)[idx*2]     = o0;
    ((float4*)out)[idx*2 + 1] = o1;
}

// ---------------- host launcher ----------------
extern "C" void kernel_launch(void* const* d_in, const int* in_sizes, int n_in,
                              void* d_out, int out_size) {
    const float* features = (const float*)d_in[0];
    const int*   captions = (const int*)  d_in[1];
    const float* W_enc    = (const float*)d_in[2];
    const float* b_enc    = (const float*)d_in[3];
    const float* emb      = (const float*)d_in[4];
    const float* W_ih     = (const float*)d_in[5];
    const float* b_ih     = (const float*)d_in[6];
    const float* W_hh     = (const float*)d_in[7];
    const float* b_hh     = (const float*)d_in[8];
    const float* W_d2     = (const float*)d_in[9];
    const float* b_d2     = (const float*)d_in[10];
    const float* W_last   = (const float*)d_in[11];
    const float* b_last   = (const float*)d_in[12];
    float* out = (float*)d_out;

    void *pX, *pG, *ph, *pc, *phs, *pout8, *pWih, *pWhh, *pWd2, *pW8T, *plgt, *pbsum, *prs, *ppart;
    cudaGetSymbolAddress(&pX, g_X);
    cudaGetSymbolAddress(&pG, g_G);
    cudaGetSymbolAddress(&ph, g_h);
    cudaGetSymbolAddress(&pc, g_c);
    cudaGetSymbolAddress(&phs, g_hs);
    cudaGetSymbolAddress(&pout8, g_out8);
    cudaGetSymbolAddress(&pWih, g_Wih);
    cudaGetSymbolAddress(&pWhh, g_Whh);
    cudaGetSymbolAddress(&pWd2, g_Wd2);
    cudaGetSymbolAddress(&pW8T, g_W8T);
    cudaGetSymbolAddress(&plgt, g_lgt);
    cudaGetSymbolAddress(&pbsum, g_bsum);
    cudaGetSymbolAddress(&prs, g_rs);
    cudaGetSymbolAddress(&ppart, g_part);

    __nv_bfloat16* X     = (__nv_bfloat16*)pX;
    float*         G     = (float*)pG;
    __nv_bfloat16* h     = (__nv_bfloat16*)ph;
    float*         c     = (float*)pc;
    __nv_bfloat16* hs    = (__nv_bfloat16*)phs;
    uint8_t*       out8  = (uint8_t*)pout8;
    __nv_bfloat16* Wih   = (__nv_bfloat16*)pWih;
    __nv_bfloat16* Whh   = (__nv_bfloat16*)pWhh;
    __nv_bfloat16* Wd2   = (__nv_bfloat16*)pWd2;
    uint8_t*       W8T   = (uint8_t*)pW8T;
    __nv_bfloat16* lgt   = (__nv_bfloat16*)plgt;
    float*         bsum  = (float*)pbsum;
    float*         rs    = (float*)prs;
    float*         part  = (float*)ppart;

    const int SMEM_T = 2*(128*40 + 256*40)*2;
    const int SMEM_P = 128*PW*2 + 16*PW*2 + 16*PGP*4;
    const int SMEM_B8 = NSTG * STG2;    // 98304
    cudaFuncSetAttribute(gemm2<128,256,32,64,64>,
                         cudaFuncAttributeMaxDynamicSharedMemorySize, SMEM_T);
    cudaFuncSetAttribute(lstm_persist,
                         cudaFuncAttributeMaxDynamicSharedMemorySize, SMEM_P);
    cudaFuncSetAttribute(gemm_big8,
                         cudaFuncAttributeMaxDynamicSharedMemorySize, SMEM_B8);

    // side stream + fork/join events (created once, on the uncaptured correctness call)
    static cudaStream_t s2 = nullptr;
    static cudaEvent_t evFork = nullptr, evJoin = nullptr;
    if (!s2) {
        cudaStreamCreateWithFlags(&s2, cudaStreamNonBlocking);
        cudaEventCreateWithFlags(&evFork, cudaEventDisableTiming);
        cudaEventCreateWithFlags(&evJoin, cudaEventDisableTiming);
    }

    // fork: W_last transpose runs on s2 concurrently with the LSTM chain
    cudaEventRecord(evFork, 0);
    cudaStreamWaitEvent(s2, evFork, 0);
    transpose_f2f8<<<dim3(VV/32, DD2/128), 256, 0, s2>>>(W_last, W8T);
    cudaEventRecord(evJoin, s2);

    // default stream: prologue (minus transpose)
    prep_main<<<NB_CV + NB_FT + NB_GA, 256>>>(
        (const float4*)W_ih, Wih, (const float4*)W_hh, Whh, (const float4*)W_d2, Wd2,
        b_ih, b_hh, bsum,
        features, W_enc, b_enc, captions, emb, X);

    // G = X @ W_ih^T + (b_ih + b_hh)
    gemm2<128,256,32,64,64>
        <<<dim3(MM/128, G4/256), 256, SMEM_T>>>(X, Wih, MM, G4, EE, bsum, G);

    // persistent LSTM + fused d2 GEMM -> out8
    lstm_persist<<<128, 256, SMEM_P>>>(Whh, G, c, h, hs, Wd2, b_d2, out8);

    // join: W8T must be ready before the big GEMM
    cudaStreamWaitEvent(0, evJoin, 0);

    // big fp8 GEMM (profiled slot 4 on default stream)
    gemm_big8<<<dim3(MM/MT2, VV/NT2), 256, SMEM_B8>>>(out8, W8T, b_last, lgt, part);

    // softmax
    partred_kernel<<<MM, 256>>>(part, rs);
    normexp_kernel<<<(int)(((long)MM*VV/8 + 255)/256), 256>>>(lgt, rs, out);
}

// round 14
// speedup vs baseline: 1.0906x; 1.0187x over previous
#include <cuda_runtime.h>
#include <cuda_bf16.h>
#include <cuda_fp8.h>
#include <mma.h>
#include <cstdint>

using namespace nvcuda;

#define BB   128
#define TT   17
#define EE   512
#define HH   512
#define VV   32000
#define DD2  1024
#define MM   (BB*TT)     // 2176
#define G4   (4*HH)      // 2048

// big fp8 gemm tiling: 128x128, 2 CTAs/SM (R10 config)
#define MT2  128
#define NT2  128
#define BKB  128
#define KIT  (DD2/BKB)             // 8
#define STG2 (MT2*BKB + NT2*BKB)   // 32768
#define NSTG 3
#define NPART (VV/NT2)             // 250
#define FP8_SCALE 64.0f
#define FP8_INV   (1.0f/4096.0f)

// ---------------- scratch ----------------
__device__ __nv_bfloat16 g_X   [MM*EE];
__device__ float         g_G   [MM*G4];
__device__ __nv_bfloat16 g_h   [BB*HH];
__device__ float         g_c   [BB*HH];
__device__ __nv_bfloat16 g_hs  [MM*HH];
__device__ uint8_t       g_out8[MM*DD2];
__device__ __nv_bfloat16 g_Wih [G4*EE];
__device__ __nv_bfloat16 g_Whh [G4*HH];
__device__ __nv_bfloat16 g_Wd2 [HH*DD2];
__device__ uint8_t       g_W8T [(long)VV*DD2];
__device__ __nv_bfloat16 g_lgt [(long)MM*VV];
__device__ float         g_bsum[G4];
__device__ float         g_rs  [MM];
__device__ float         g_part[(long)MM*NPART];
__device__ unsigned      g_barcnt = 0;
__device__ unsigned      g_gen    = 0;

// ---------------- async copy helpers ----------------
__device__ __forceinline__ void cpa16(void* dst, const void* src) {
    uint32_t d = (uint32_t)__cvta_generic_to_shared(dst);
    asm volatile("cp.async.cg.shared.global [%0], [%1], 16;\n" :: "r"(d), "l"(src));
}
__device__ __forceinline__ void cpa16s(uint32_t d, const void* src) {
    asm volatile("cp.async.cg.shared.global [%0], [%1], 16;\n" :: "r"(d), "l"(src));
}
__device__ __forceinline__ void cpa_commit() { asm volatile("cp.async.commit_group;\n"); }
template<int N> __device__ __forceinline__ void cpa_wait() {
    asm volatile("cp.async.wait_group %0;\n" :: "n"(N));
}
__device__ __forceinline__ uint32_t sw128(uint32_t off) { return off ^ ((off >> 3) & 0x70); }

__device__ __forceinline__ void ldsm_x4(uint32_t& d0, uint32_t& d1, uint32_t& d2, uint32_t& d3,
                                        uint32_t addr) {
    asm volatile("ldmatrix.sync.aligned.m8n8.x4.shared.b16 {%0,%1,%2,%3}, [%4];"
                 : "=r"(d0), "=r"(d1), "=r"(d2), "=r"(d3) : "r"(addr));
}
__device__ __forceinline__ void qmma(float* c, const uint32_t* a, const uint32_t* b) {
    asm volatile("mma.sync.aligned.m16n8k32.row.col.f32.e4m3.e4m3.f32 "
                 "{%0,%1,%2,%3}, {%4,%5,%6,%7}, {%8,%9}, {%0,%1,%2,%3};"
                 : "+f"(c[0]), "+f"(c[1]), "+f"(c[2]), "+f"(c[3])
                 : "r"(a[0]), "r"(a[1]), "r"(a[2]), "r"(a[3]), "r"(b[0]), "r"(b[1]));
}

// ---------------- fused prologue (R10: transpose + converts + feat + gather) ----------------
#define NB_TR  8000
#define NB_CV  2568
#define NB_FT  256
#define NB_GA  4096
__global__ void __launch_bounds__(256) prep(
    const float* __restrict__ W_last, uint8_t* __restrict__ W8T,
    const float4* __restrict__ Wih_s, __nv_bfloat16* __restrict__ Wih_d,
    const float4* __restrict__ Whh_s, __nv_bfloat16* __restrict__ Whh_d,
    const float4* __restrict__ Wd2_s, __nv_bfloat16* __restrict__ Wd2_d,
    const float* __restrict__ bih, const float* __restrict__ bhh, float* __restrict__ bsum,
    const float* __restrict__ features, const float* __restrict__ W_enc,
    const float* __restrict__ b_enc, const int* __restrict__ captions,
    const float* __restrict__ emb, __nv_bfloat16* __restrict__ X)
{
    __shared__ float tile[128][33];
    int bid = blockIdx.x, tid = threadIdx.x;

    if (bid < NB_TR) {
        int n0 = (bid % 1000) * 32, k0 = (bid / 1000) * 128;
        int tx = tid & 31, ty = tid >> 5;
#pragma unroll
        for (int r = 0; r < 128; r += 8)
            tile[r + ty][tx] = W_last[(long)(k0 + r + ty) * VV + n0 + tx];
        __syncthreads();
#pragma unroll
        for (int nn = 0; nn < 32; nn += 8) {
            int n = n0 + nn + ty;
            uchar4 p;
            p.x = (uint8_t)__nv_cvt_float_to_fp8(tile[tx*4+0][nn+ty] * FP8_SCALE, __NV_SATFINITE, __NV_E4M3);
            p.y = (uint8_t)__nv_cvt_float_to_fp8(tile[tx*4+1][nn+ty] * FP8_SCALE, __NV_SATFINITE, __NV_E4M3);
            p.z = (uint8_t)__nv_cvt_float_to_fp8(tile[tx*4+2][nn+ty] * FP8_SCALE, __NV_SATFINITE, __NV_E4M3);
            p.w = (uint8_t)__nv_cvt_float_to_fp8(tile[tx*4+3][nn+ty] * FP8_SCALE, __NV_SATFINITE, __NV_E4M3);
            *(uchar4*)&W8T[(long)n * DD2 + k0 + tx*4] = p;
        }
        return;
    }
    if (bid < NB_TR + NB_CV) {
        int b2 = bid - NB_TR;
        const float4* src;
        __nv_bfloat16* dst;
        int i;
        if (b2 < 1024)       { src = Wih_s; dst = Wih_d; i = b2*256 + tid; }
        else if (b2 < 2048)  { src = Whh_s; dst = Whh_d; i = (b2-1024)*256 + tid; }
        else if (b2 < 2560)  { src = Wd2_s; dst = Wd2_d; i = (b2-2048)*256 + tid; }
        else {
            int j = (b2-2560)*256 + tid;
            if (j < G4) bsum[j] = bih[j] + bhh[j];
            return;
        }
        float4 v = src[i];
        __nv_bfloat16 t[4];
        t[0] = __float2bfloat16(v.x);
        t[1] = __float2bfloat16(v.y);
        t[2] = __float2bfloat16(v.z);
        t[3] = __float2bfloat16(v.w);
        *(uint2*)&dst[4*i] = *(uint2*)t;
        return;
    }
    if (bid < NB_TR + NB_CV + NB_FT) {
        int b2 = bid - NB_TR - NB_CV;
        int b = b2 >> 1;
        int n = (b2 & 1) * 256 + tid;
        float* fs = &tile[0][0];
        fs[tid]       = features[b*EE + tid];
        fs[tid + 256] = features[b*EE + tid + 256];
        __syncthreads();
        float s = b_enc[n];
#pragma unroll 8
        for (int k = 0; k < EE; k++) s += fs[k] * W_enc[k*EE + n];
        X[(b*TT + 0)*EE + n] = __float2bfloat16(s);
        return;
    }
    int idx = (bid - NB_TR - NB_CV - NB_FT) * 256 + tid;
    int k = idx & (EE-1);
    int r = (idx >> 9) & 15;
    int b = idx >> 13;
    int cap = captions[b*TT + r];
    X[(b*TT + r + 1)*EE + k] = __float2bfloat16(emb[cap*EE + k]);
}

// ---------------- wmma GEMM (G gemm): Cf = A @ B^T + bias ----------------
template<int BM, int BN, int BK, int WM, int WN>
__global__ void __launch_bounds__(256)
gemm2(const __nv_bfloat16* __restrict__ A, const __nv_bfloat16* __restrict__ B,
      int M, int N, int K, const float* __restrict__ bias, float* __restrict__ Cf)
{
    constexpr int BKP = BK + 8;
    constexpr int ASZ = BM * BKP;
    constexpr int BSZ = BN * BKP;
    constexpr int WARPS_N = BN / WN;
    constexpr int FM = WM / 16;
    constexpr int FN = WN / 16;

    extern __shared__ __nv_bfloat16 dynsm[];
    __nv_bfloat16* Asb[2] = { dynsm, dynsm + ASZ };
    __nv_bfloat16* Bsb[2] = { dynsm + 2*ASZ, dynsm + 2*ASZ + BSZ };

    int tid  = threadIdx.x;
    int lane = tid & 31;
    int wid  = tid >> 5;
    int wr   = wid / WARPS_N;
    int wc   = wid % WARPS_N;
    int mBase = blockIdx.x * BM;
    int nBase = blockIdx.y * BN;

    wmma::fragment<wmma::accumulator, 16, 16, 16, float> acc[FM][FN];
#pragma unroll
    for (int i = 0; i < FM; i++)
#pragma unroll
        for (int j = 0; j < FN; j++)
            wmma::fill_fragment(acc[i][j], 0.0f);

    auto loadA = [&](int buf, int k0) {
        constexpr int CPR = BK / 8;
#pragma unroll
        for (int i = 0; i < BM*CPR/256; i++) {
            int cid = tid + i*256;
            int r = cid / CPR, cc = (cid % CPR) * 8;
            cpa16(&Asb[buf][r*BKP + cc], &A[(long)(mBase + r)*K + k0 + cc]);
        }
    };
    auto loadB = [&](int buf, int k0) {
        constexpr int CPR = BK / 8;
#pragma unroll
        for (int i = 0; i < BN*CPR/256; i++) {
            int cid = tid + i*256;
            int r = cid / CPR, cc = (cid % CPR) * 8;
            cpa16(&Bsb[buf][r*BKP + cc], &B[(long)(nBase + r)*K + k0 + cc]);
        }
    };

    loadA(0, 0); loadB(0, 0); cpa_commit();
    int KTn = K / BK;
    for (int kt = 0; kt < KTn; kt++) {
        int buf = kt & 1;
        cpa_wait<0>();
        __syncthreads();
        if (kt + 1 < KTn) { loadA(buf^1, (kt+1)*BK); loadB(buf^1, (kt+1)*BK); cpa_commit(); }
#pragma unroll
        for (int kk = 0; kk < BK; kk += 16) {
            wmma::fragment<wmma::matrix_a, 16, 16, 16, __nv_bfloat16, wmma::row_major> af[FM];
#pragma unroll
            for (int i = 0; i < FM; i++)
                wmma::load_matrix_sync(af[i], &Asb[buf][(wr*WM + i*16)*BKP + kk], BKP);
#pragma unroll
            for (int j = 0; j < FN; j++) {
                wmma::fragment<wmma::matrix_b, 16, 16, 16, __nv_bfloat16, wmma::col_major> bf;
                wmma::load_matrix_sync(bf, &Bsb[buf][(wc*WN + j*16)*BKP + kk], BKP);
#pragma unroll
                for (int i = 0; i < FM; i++)
                    wmma::mma_sync(acc[i][j], af[i], bf, acc[i][j]);
            }
        }
        __syncthreads();
    }

    float* myst = (float*)dynsm + wid * 256;
#pragma unroll
    for (int i = 0; i < FM; i++) {
#pragma unroll
        for (int j = 0; j < FN; j++) {
            wmma::store_matrix_sync(myst, acc[i][j], 16, wmma::mem_row_major);
            __syncwarp();
            int gr0 = mBase + wr*WM + i*16;
            int gc0 = nBase + wc*WN + j*16;
#pragma unroll
            for (int e = lane; e < 256; e += 32) {
                int rr = e >> 4, cc2 = e & 15;
                Cf[(long)(gr0 + rr)*N + (gc0 + cc2)] = myst[e] + bias[gc0 + cc2];
            }
            __syncwarp();
        }
    }
}

// ---------------- persistent LSTM + fused d2 GEMM (G-prefetch + 2-chain wmma) ----------------
#define PW  520
#define PGP 132
#define D2_AP  72
#define D2_BP  136
#define GSM_OFF (128*PW*2 + 16*PW*2 + 16*PGP*4)     // 158208
__global__ void __launch_bounds__(256) lstm_persist(
    const __nv_bfloat16* __restrict__ Whh, const float* __restrict__ G,
    float* __restrict__ c, __nv_bfloat16* __restrict__ h, __nv_bfloat16* __restrict__ hs,
    const __nv_bfloat16* __restrict__ Wd2, const float* __restrict__ b_d2,
    uint8_t* __restrict__ out8)
{
    extern __shared__ char smraw[];
    __nv_bfloat16* Wsm = (__nv_bfloat16*)smraw;                          // 128 x PW
    __nv_bfloat16* As  = (__nv_bfloat16*)(smraw + 128*PW*2);             // 16 x PW
    float*         Gst = (float*)(smraw + 128*PW*2 + 16*PW*2);           // 16 x PGP
    float*         Gsm = (float*)(smraw + GSM_OFF);                      // 2 x 16 x 128

    int tid = threadIdx.x, lane = tid & 31, wid = tid >> 5;
    int jc0 = (blockIdx.x >> 3) * 32;
    int b0  = (blockIdx.x & 7) * 16;

    // prefetch gate slab G(t) -> Gsm[buf]: 16 rows x 4 gates x 32 floats
    auto loadG = [&](int buf, int t) {
#pragma unroll
        for (int i = 0; i < 2; i++) {
            int cid = tid + i*256;                  // 512 chunks of 16B
            int row = cid >> 5, seg = (cid >> 3) & 3, off = (cid & 7) * 4;
            cpa16(&Gsm[buf*2048 + row*128 + seg*32 + off],
                  &G[((long)(b0 + row)*TT + t)*G4 + seg*512 + jc0 + off]);
        }
        cpa_commit();
    };

    loadG(0, 0);

    // preload W slice
#pragma unroll
    for (int i = 0; i < 32; i++) {
        int e = tid + i*256;
        int gr = e >> 6, cc = (e & 63) * 8;
        int gate = gr >> 5, r = gr & 31;
        *(uint4*)&Wsm[gr*PW + cc] = *(const uint4*)&Whh[(long)(gate*512 + jc0 + r)*512 + cc];
    }
    __syncthreads();

    auto gridbar = [&]() {
        __threadfence();
        __syncthreads();
        if (tid == 0) {
            unsigned old = *(volatile unsigned*)&g_gen;
            unsigned a = atomicAdd(&g_barcnt, 1);
            if (a == gridDim.x - 1) {
                g_barcnt = 0;
                __threadfence();
                atomicAdd(&g_gen, 1);
            } else {
                while (*(volatile unsigned*)&g_gen == old) { }
            }
        }
        __syncthreads();
        __threadfence();
    };

    for (int t = 0; t < TT; t++) {
        int gbuf = t & 1;

        if (t > 0) {
            // h slice via cp.async (cg -> L1-bypass, L2-coherent with cross-SM writes)
#pragma unroll
            for (int i = 0; i < 4; i++) {
                int e = tid + i*256;
                int r = e >> 6, cc = (e & 63) * 8;
                cpa16(&As[r*PW + cc], &h[(b0 + r)*HH + cc]);
            }
            cpa_commit();
        }
        cpa_wait<0>();          // waits G(t) prefetch (+ h group when t>0)
        __syncthreads();

        if (t > 0) {
            // 2 independent accumulator chains over K halves (halved serial MMA depth)
            wmma::fragment<wmma::accumulator, 16, 16, 16, float> a0, a1;
            wmma::fill_fragment(a0, 0.0f);
            wmma::fill_fragment(a1, 0.0f);
#pragma unroll 4
            for (int kk = 0; kk < 256; kk += 16) {
                {
                    wmma::fragment<wmma::matrix_a, 16, 16, 16, __nv_bfloat16, wmma::row_major> af;
                    wmma::load_matrix_sync(af, &As[kk], PW);
                    wmma::fragment<wmma::matrix_b, 16, 16, 16, __nv_bfloat16, wmma::col_major> bf;
                    wmma::load_matrix_sync(bf, &Wsm[(wid*16)*PW + kk], PW);
                    wmma::mma_sync(a0, af, bf, a0);
                }
                {
                    wmma::fragment<wmma::matrix_a, 16, 16, 16, __nv_bfloat16, wmma::row_major> af;
                    wmma::load_matrix_sync(af, &As[kk + 256], PW);
                    wmma::fragment<wmma::matrix_b, 16, 16, 16, __nv_bfloat16, wmma::col_major> bf;
                    wmma::load_matrix_sync(bf, &Wsm[(wid*16)*PW + kk + 256], PW);
                    wmma::mma_sync(a1, af, bf, a1);
                }
            }
#pragma unroll
            for (int e2 = 0; e2 < a0.num_elements; e2++) a0.x[e2] += a1.x[e2];
            wmma::store_matrix_sync(&Gst[wid*16], a0, PGP, wmma::mem_row_major);
            __syncthreads();
        }

        // prefetch next step's gate slab while the cell runs
        if (t + 1 < TT) loadG(gbuf ^ 1, t + 1);

        // fused cell (gates now read from smem)
#pragma unroll
        for (int i = 0; i < 2; i++) {
            int e = i*256 + tid;
            int jr = e & 31, bl = e >> 5;
            int b = b0 + bl;
            int j = jc0 + jr;
            const float* gr2 = &Gsm[gbuf*2048 + bl*128];
            float s0 = 0.f, s1 = 0.f, s2 = 0.f, s3 = 0.f, cp = 0.f;
            if (t > 0) {
                s0 = Gst[bl*PGP + jr];
                s1 = Gst[bl*PGP + 32 + jr];
                s2 = Gst[bl*PGP + 64 + jr];
                s3 = Gst[bl*PGP + 96 + jr];
                cp = c[b*HH + j];
            }
            float gi = gr2[jr]        + s0;
            float gf = gr2[32 + jr]   + s1;
            float gg = gr2[64 + jr]   + s2;
            float go = gr2[96 + jr]   + s3;
            float i_ = 1.f / (1.f + __expf(-gi));
            float f_ = 1.f / (1.f + __expf(-gf));
            float o_ = 1.f / (1.f + __expf(-go));
            float g_ = tanhf(gg);
            float cn = f_*cp + i_*g_;
            float hn = o_*tanhf(cn);
            c[b*HH + j] = cn;
            __nv_bfloat16 hb = __float2bfloat16(hn);
            h[b*HH + j] = hb;
            hs[(long)(b*TT + t)*HH + j] = hb;
        }

        if (t < TT-1) gridbar();
    }

    gridbar();

    // ---------- fused d2 GEMM ----------
    __nv_bfloat16* As2 = (__nv_bfloat16*)smraw;
    __nv_bfloat16* Bs2 = (__nv_bfloat16*)(smraw + 2*128*D2_AP*2);
    float*         est = (float*)(smraw + 2*128*D2_AP*2 + 2*64*D2_BP*2);

    int wr2 = wid >> 1, wc2 = wid & 1;

    for (int tile = blockIdx.x; tile < 136; tile += gridDim.x) {
        int mBase = (tile % 17) * 128;
        int nBase = (tile / 17) * 128;
        __syncthreads();

        wmma::fragment<wmma::accumulator, 16, 16, 16, float> acc[2][4];
#pragma unroll
        for (int i = 0; i < 2; i++)
#pragma unroll
            for (int j = 0; j < 4; j++)
                wmma::fill_fragment(acc[i][j], 0.0f);

        auto loadA2 = [&](int buf, int k0) {
#pragma unroll
            for (int i = 0; i < 4; i++) {
                int cid = tid + i*256;
                int r = cid >> 3, cc = (cid & 7) * 8;
                cpa16(&As2[buf*128*D2_AP + r*D2_AP + cc], &hs[(long)(mBase + r)*HH + k0 + cc]);
            }
        };
        auto loadB2 = [&](int buf, int k0) {
#pragma unroll
            for (int i = 0; i < 4; i++) {
                int cid = tid + i*256;
                int r = cid >> 4, cc = (cid & 15) * 8;
                cpa16(&Bs2[buf*64*D2_BP + r*D2_BP + cc], &Wd2[(long)(k0 + r)*DD2 + nBase + cc]);
            }
        };

        loadA2(0, 0); loadB2(0, 0); cpa_commit();
        for (int kt = 0; kt < 8; kt++) {
            int buf = kt & 1;
            cpa_wait<0>();
            __syncthreads();
            if (kt + 1 < 8) { loadA2(buf^1, (kt+1)*64); loadB2(buf^1, (kt+1)*64); cpa_commit(); }
#pragma unroll
            for (int kk = 0; kk < 64; kk += 16) {
                wmma::fragment<wmma::matrix_a, 16, 16, 16, __nv_bfloat16, wmma::row_major> af[2];
#pragma unroll
                for (int i = 0; i < 2; i++)
                    wmma::load_matrix_sync(af[i], &As2[buf*128*D2_AP + (wr2*32 + i*16)*D2_AP + kk], D2_AP);
#pragma unroll
                for (int j = 0; j < 4; j++) {
                    wmma::fragment<wmma::matrix_b, 16, 16, 16, __nv_bfloat16, wmma::row_major> bf;
                    wmma::load_matrix_sync(bf, &Bs2[buf*64*D2_BP + kk*D2_BP + wc2*64 + j*16], D2_BP);
#pragma unroll
                    for (int i = 0; i < 2; i++)
                        wmma::mma_sync(acc[i][j], af[i], bf, acc[i][j]);
                }
            }
            __syncthreads();
        }

        float* myst = &est[wid * 256];
#pragma unroll
        for (int i = 0; i < 2; i++) {
#pragma unroll
            for (int j = 0; j < 4; j++) {
                wmma::store_matrix_sync(myst, acc[i][j], 16, wmma::mem_row_major);
                __syncwarp();
                int gr0 = mBase + wr2*32 + i*16;
                int gc0 = nBase + wc2*64 + j*16;
#pragma unroll
                for (int e = lane; e < 256; e += 32) {
                    int rr = e >> 4, cc2 = e & 15;
                    out8[(long)(gr0 + rr)*DD2 + (gc0 + cc2)] =
                        (uint8_t)__nv_cvt_float_to_fp8(
                            fmaxf(myst[e] + b_d2[gc0 + cc2], 0.f) * FP8_SCALE,
                            __NV_SATFINITE, __NV_E4M3);
                }
                __syncwarp();
            }
        }
    }
}

// ---------------- big fp8 GEMM: 128x128, 256 thr, 3-stage, 2 CTAs/SM (R10 exact) ----------------
__global__ void __launch_bounds__(256, 2) gemm_big8(
    const uint8_t* __restrict__ A8, const uint8_t* __restrict__ B8,
    const float* __restrict__ bias, __nv_bfloat16* __restrict__ lgt, float* __restrict__ part)
{
    extern __shared__ uint8_t sm8[];
    __shared__ float pss[128][2];
    uint32_t sb = (uint32_t)__cvta_generic_to_shared(sm8);

    int tid  = threadIdx.x;
    int lane = tid & 31;
    int wid  = tid >> 5;
    int wr   = wid >> 1;
    int wc   = wid & 1;
    int mBase = blockIdx.x * MT2;
    int nBase = blockIdx.y * NT2;

    float acc[2][8][4];
#pragma unroll
    for (int f = 0; f < 2; f++)
#pragma unroll
        for (int j = 0; j < 8; j++)
#pragma unroll
            for (int e = 0; e < 4; e++) acc[f][j][e] = 0.f;

    const uint8_t* pA = A8 + (long)(mBase + (tid >> 3)) * DD2 + (tid & 7) * 16;
    const uint8_t* pB = B8 + (long)(nBase + (tid >> 3)) * DD2 + (tid & 7) * 16;
    const uint32_t dA = sb + sw128((uint32_t)((tid >> 3) * 128 + (tid & 7) * 16));
    const uint32_t dB = dA + MT2 * BKB;

    auto loadst = [&](int st, int k0) {
        uint32_t ab = dA + st * STG2;
        uint32_t bb = dB + st * STG2;
#pragma unroll
        for (int i = 0; i < 4; i++)
            cpa16s(ab + i * 4096, pA + k0 + i * 32 * DD2);
#pragma unroll
        for (int i = 0; i < 4; i++)
            cpa16s(bb + i * 4096, pB + k0 + i * 32 * DD2);
    };

    loadst(0, 0);       cpa_commit();
    loadst(1, BKB);     cpa_commit();

    int lrow = lane & 15;
    int lcol = (lane & 16) ? 16 : 0;
    uint32_t rowA[2], keyA[2];
#pragma unroll
    for (int f = 0; f < 2; f++) {
        int rr = wr * 32 + f * 16 + lrow;
        rowA[f] = (uint32_t)(rr * 128);
        keyA[f] = (uint32_t)((rr & 7) * 16);
    }
    uint32_t rowB[4], keyB[4];
#pragma unroll
    for (int g = 0; g < 4; g++) {
        int nn = wc * 64 + g * 16 + lrow;
        rowB[g] = (uint32_t)(MT2 * BKB + nn * 128);
        keyB[g] = (uint32_t)((nn & 7) * 16);
    }

    for (int kt = 0; kt < KIT; kt++) {
        int st = kt - (kt / 3) * 3;
        cpa_wait<1>();
        __syncthreads();
        if (kt + 2 < KIT) {
            int st2 = kt + 2;
            loadst(st2 - (st2 / 3) * 3, st2 * BKB);
        }
        cpa_commit();

        uint32_t stbase = sb + st * STG2;
#pragma unroll
        for (int s = 0; s < 4; s++) {
            uint32_t bytec = (uint32_t)(s * 32 + lcol);
            uint32_t a[2][4];
#pragma unroll
            for (int f = 0; f < 2; f++)
                ldsm_x4(a[f][0], a[f][1], a[f][2], a[f][3],
                        stbase + rowA[f] + (bytec ^ keyA[f]));
#pragma unroll
            for (int half = 0; half < 2; half++) {
                uint32_t b[4][2];
#pragma unroll
                for (int g = 0; g < 2; g++) {
                    uint32_t r0, r1, r2, r3;
                    ldsm_x4(r0, r1, r2, r3,
                            stbase + rowB[half*2 + g] + (bytec ^ keyB[half*2 + g]));
                    b[g*2][0] = r0; b[g*2+1][0] = r1;
                    b[g*2][1] = r2; b[g*2+1][1] = r3;
                }
#pragma unroll
                for (int f = 0; f < 2; f++)
#pragma unroll
                    for (int j = 0; j < 4; j++)
                        qmma(acc[f][half*4 + j], a[f], b[j]);
            }
        }
    }

    float ps[4] = {0.f, 0.f, 0.f, 0.f};
    long rbase = mBase + wr * 32 + (lane >> 2);
#pragma unroll
    for (int f = 0; f < 2; f++) {
        long r0 = rbase + f * 16;
#pragma unroll
        for (int j = 0; j < 8; j++) {
            int col = nBase + wc * 64 + j * 8 + (lane & 3) * 2;
            float2 bv = *(const float2*)&bias[col];
            float l0 = acc[f][j][0] * FP8_INV + bv.x;
            float l1 = acc[f][j][1] * FP8_INV + bv.y;
            float l2 = acc[f][j][2] * FP8_INV + bv.x;
            float l3 = acc[f][j][3] * FP8_INV + bv.y;
            ps[f*2]     += __expf(l0) + __expf(l1);
            ps[f*2 + 1] += __expf(l2) + __expf(l3);
            *(__nv_bfloat162*)&lgt[r0 * VV + col]       = __floats2bfloat162_rn(l0, l1);
            *(__nv_bfloat162*)&lgt[(r0 + 8) * VV + col] = __floats2bfloat162_rn(l2, l3);
        }
    }
#pragma unroll
    for (int k = 0; k < 4; k++) {
        ps[k] += __shfl_xor_sync(0xffffffffu, ps[k], 1);
        ps[k] += __shfl_xor_sync(0xffffffffu, ps[k], 2);
    }
    if ((lane & 3) == 0) {
#pragma unroll
        for (int f = 0; f < 2; f++) {
            pss[wr*32 + f*16 + (lane >> 2)][wc]     = ps[f*2];
            pss[wr*32 + f*16 + 8 + (lane >> 2)][wc] = ps[f*2 + 1];
        }
    }
    __syncthreads();
    if (tid < 128)
        part[(long)(mBase + tid) * NPART + blockIdx.y] = pss[tid][0] + pss[tid][1];
}

// ---------------- softmax: reduce partials, grid-stride exp+normalize ----------------
__global__ void partred_kernel(const float* __restrict__ part, float* __restrict__ rs) {
    __shared__ float red[256];
    int row = blockIdx.x, t = threadIdx.x;
    float s = (t < NPART) ? part[(long)row*NPART + t] : 0.f;
    red[t] = s;
    __syncthreads();
    for (int st = 128; st > 0; st >>= 1) {
        if (t < st) red[t] += red[t + st];
        __syncthreads();
    }
    if (t == 0) rs[row] = 1.f / red[0];
}

__global__ void normexp_kernel(const __nv_bfloat16* __restrict__ lgt,
                               const float* __restrict__ rs, float* __restrict__ out) {
    long idx = (long)blockIdx.x * blockDim.x + threadIdx.x;
    const long tot = (long)MM * VV / 8;
    if (idx >= tot) return;
    int row = (int)((idx * 8) / VV);
    float inv = rs[row];
    uint4 raw = ((const uint4*)lgt)[idx];
    __nv_bfloat162* bp = (__nv_bfloat162*)&raw;
    float4 o0, o1;
    float2 a0 = __bfloat1622float2(bp[0]);
    float2 a1 = __bfloat1622float2(bp[1]);
    float2 a2 = __bfloat1622float2(bp[2]);
    float2 a3 = __bfloat1622float2(bp[3]);
    o0.x = __expf(a0.x) * inv; o0.y = __expf(a0.y) * inv;
    o0.z = __expf(a1.x) * inv; o0.w = __expf(a1.y) * inv;
    o1.x = __expf(a2.x) * inv; o1.y = __expf(a2.y) * inv;
    o1.z = __expf(a3.x) * inv; o1.w = __expf(a3.y) * inv;
    ((float4*)out)[idx*2]     = o0;
    ((float4*)out)[idx*2 + 1] = o1;
}

// ---------------- host launcher ----------------
extern "C" void kernel_launch(void* const* d_in, const int* in_sizes, int n_in,
                              void* d_out, int out_size) {
    const float* features = (const float*)d_in[0];
    const int*   captions = (const int*)  d_in[1];
    const float* W_enc    = (const float*)d_in[2];
    const float* b_enc    = (const float*)d_in[3];
    const float* emb      = (const float*)d_in[4];
    const float* W_ih     = (const float*)d_in[5];
    const float* b_ih     = (const float*)d_in[6];
    const float* W_hh     = (const float*)d_in[7];
    const float* b_hh     = (const float*)d_in[8];
    const float* W_d2     = (const float*)d_in[9];
    const float* b_d2     = (const float*)d_in[10];
    const float* W_last   = (const float*)d_in[11];
    const float* b_last   = (const float*)d_in[12];
    float* out = (float*)d_out;

    void *pX, *pG, *ph, *pc, *phs, *pout8, *pWih, *pWhh, *pWd2, *pW8T, *plgt, *pbsum, *prs, *ppart;
    cudaGetSymbolAddress(&pX, g_X);
    cudaGetSymbolAddress(&pG, g_G);
    cudaGetSymbolAddress(&ph, g_h);
    cudaGetSymbolAddress(&pc, g_c);
    cudaGetSymbolAddress(&phs, g_hs);
    cudaGetSymbolAddress(&pout8, g_out8);
    cudaGetSymbolAddress(&pWih, g_Wih);
    cudaGetSymbolAddress(&pWhh, g_Whh);
    cudaGetSymbolAddress(&pWd2, g_Wd2);
    cudaGetSymbolAddress(&pW8T, g_W8T);
    cudaGetSymbolAddress(&plgt, g_lgt);
    cudaGetSymbolAddress(&pbsum, g_bsum);
    cudaGetSymbolAddress(&prs, g_rs);
    cudaGetSymbolAddress(&ppart, g_part);

    __nv_bfloat16* X     = (__nv_bfloat16*)pX;
    float*         G     = (float*)pG;
    __nv_bfloat16* h     = (__nv_bfloat16*)ph;
    float*         c     = (float*)pc;
    __nv_bfloat16* hs    = (__nv_bfloat16*)phs;
    uint8_t*       out8  = (uint8_t*)pout8;
    __nv_bfloat16* Wih   = (__nv_bfloat16*)pWih;
    __nv_bfloat16* Whh   = (__nv_bfloat16*)pWhh;
    __nv_bfloat16* Wd2   = (__nv_bfloat16*)pWd2;
    uint8_t*       W8T   = (uint8_t*)pW8T;
    __nv_bfloat16* lgt   = (__nv_bfloat16*)plgt;
    float*         bsum  = (float*)pbsum;
    float*         rs    = (float*)prs;
    float*         part  = (float*)ppart;

    const int SMEM_T = 2*(128*40 + 256*40)*2;
    const int SMEM_P = GSM_OFF + 2*16*128*4;    // 174592
    const int SMEM_B8 = NSTG * STG2;            // 98304
    cudaFuncSetAttribute(gemm2<128,256,32,64,64>,
                         cudaFuncAttributeMaxDynamicSharedMemorySize, SMEM_T);
    cudaFuncSetAttribute(lstm_persist,
                         cudaFuncAttributeMaxDynamicSharedMemorySize, SMEM_P);
    cudaFuncSetAttribute(gemm_big8,
                         cudaFuncAttributeMaxDynamicSharedMemorySize, SMEM_B8);

    // launch 1: all prologue work fused (R10 form)
    prep<<<NB_TR + NB_CV + NB_FT + NB_GA, 256>>>(
        W_last, W8T,
        (const float4*)W_ih, Wih, (const float4*)W_hh, Whh, (const float4*)W_d2, Wd2,
        b_ih, b_hh, bsum,
        features, W_enc, b_enc, captions, emb, X);

    // launch 2: G = X @ W_ih^T + (b_ih + b_hh)
    gemm2<128,256,32,64,64>
        <<<dim3(MM/128, G4/256), 256, SMEM_T>>>(X, Wih, MM, G4, EE, bsum, G);

    // launch 3: persistent LSTM + fused d2 GEMM -> out8 (profiled slot 3)
    lstm_persist<<<128, 256, SMEM_P>>>(Whh, G, c, h, hs, Wd2, b_d2, out8);

    // launch 4: big fp8 GEMM
    gemm_big8<<<dim3(MM/MT2, VV/NT2), 256, SMEM_B8>>>(out8, W8T, b_last, lgt, part);

    // softmax
    partred_kernel<<<MM, 256>>>(part, rs);
    normexp_kernel<<<(int)(((long)MM*VV/8 + 255)/256), 256>>>(lgt, rs, out);
}

// round 17
// speedup vs baseline: 1.1015x; 1.0100x over previous
#include <cuda_runtime.h>
#include <cuda_bf16.h>
#include <cuda_fp8.h>
#include <mma.h>
#include <cstdint>

using namespace nvcuda;

#define BB   128
#define TT   17
#define EE   512
#define HH   512
#define VV   32000
#define DD2  1024
#define MM   (BB*TT)     // 2176
#define G4   (4*HH)      // 2048

// big fp8 gemm tiling: 128x128, 2 CTAs/SM
#define MT2  128
#define NT2  128
#define BKB  128
#define KIT  (DD2/BKB)             // 8
#define STG2 (MT2*BKB + NT2*BKB)   // 32768
#define NSTG 3
#define NPART (VV/NT2)             // 250
#define EROW 272                   // epilogue smem row stride (bytes, 16-aligned)
#define FP8_SCALE 64.0f
#define FP8_INV   (1.0f/4096.0f)

// ---------------- scratch ----------------
__device__ __nv_bfloat16 g_X   [MM*EE];
__device__ float         g_G   [MM*G4];
__device__ __nv_bfloat16 g_h   [BB*HH];
__device__ float         g_c   [BB*HH];
__device__ __nv_bfloat16 g_hs  [MM*HH];
__device__ uint8_t       g_out8[MM*DD2];
__device__ __nv_bfloat16 g_Wih [G4*EE];
__device__ __nv_bfloat16 g_Whh [G4*HH];
__device__ __nv_bfloat16 g_Wd2 [HH*DD2];
__device__ uint8_t       g_W8T [(long)VV*DD2];
__device__ __nv_bfloat16 g_lgt [(long)MM*VV];
__device__ float         g_bsum[G4];
__device__ float         g_rs  [MM];
__device__ float         g_part[(long)MM*NPART];
__device__ unsigned      g_barcnt = 0;
__device__ unsigned      g_gen    = 0;

// ---------------- async copy helpers ----------------
__device__ __forceinline__ void cpa16(void* dst, const void* src) {
    uint32_t d = (uint32_t)__cvta_generic_to_shared(dst);
    asm volatile("cp.async.cg.shared.global [%0], [%1], 16;\n" :: "r"(d), "l"(src));
}
__device__ __forceinline__ void cpa16s(uint32_t d, const void* src) {
    asm volatile("cp.async.cg.shared.global [%0], [%1], 16;\n" :: "r"(d), "l"(src));
}
__device__ __forceinline__ void cpa_commit() { asm volatile("cp.async.commit_group;\n"); }
template<int N> __device__ __forceinline__ void cpa_wait() {
    asm volatile("cp.async.wait_group %0;\n" :: "n"(N));
}
__device__ __forceinline__ uint32_t sw128(uint32_t off) { return off ^ ((off >> 3) & 0x70); }

__device__ __forceinline__ void ldsm_x4(uint32_t& d0, uint32_t& d1, uint32_t& d2, uint32_t& d3,
                                        uint32_t addr) {
    asm volatile("ldmatrix.sync.aligned.m8n8.x4.shared.b16 {%0,%1,%2,%3}, [%4];"
                 : "=r"(d0), "=r"(d1), "=r"(d2), "=r"(d3) : "r"(addr));
}
__device__ __forceinline__ void qmma(float* c, const uint32_t* a, const uint32_t* b) {
    asm volatile("mma.sync.aligned.m16n8k32.row.col.f32.e4m3.e4m3.f32 "
                 "{%0,%1,%2,%3}, {%4,%5,%6,%7}, {%8,%9}, {%0,%1,%2,%3};"
                 : "+f"(c[0]), "+f"(c[1]), "+f"(c[2]), "+f"(c[3])
                 : "r"(a[0]), "r"(a[1]), "r"(a[2]), "r"(a[3]), "r"(b[0]), "r"(b[1]));
}
__device__ __forceinline__ uint32_t bf2_to_u32(float lo, float hi) {
    __nv_bfloat162 p = __floats2bfloat162_rn(lo, hi);
    uint32_t u;
    memcpy(&u, &p, 4);
    return u;
}

// ---------------- fused prologue ----------------
#define NB_TR  8000
#define NB_CV  2568
#define NB_FT  256
#define NB_GA  4096
__global__ void __launch_bounds__(256) prep(
    const float* __restrict__ W_last, uint8_t* __restrict__ W8T,
    const float4* __restrict__ Wih_s, __nv_bfloat16* __restrict__ Wih_d,
    const float4* __restrict__ Whh_s, __nv_bfloat16* __restrict__ Whh_d,
    const float4* __restrict__ Wd2_s, __nv_bfloat16* __restrict__ Wd2_d,
    const float* __restrict__ bih, const float* __restrict__ bhh, float* __restrict__ bsum,
    const float* __restrict__ features, const float* __restrict__ W_enc,
    const float* __restrict__ b_enc, const int* __restrict__ captions,
    const float* __restrict__ emb, __nv_bfloat16* __restrict__ X)
{
    __shared__ float tile[128][33];
    int bid = blockIdx.x, tid = threadIdx.x;

    if (bid < NB_TR) {
        int n0 = (bid % 1000) * 32, k0 = (bid / 1000) * 128;
        int tx = tid & 31, ty = tid >> 5;
#pragma unroll
        for (int r = 0; r < 128; r += 8)
            tile[r + ty][tx] = W_last[(long)(k0 + r + ty) * VV + n0 + tx];
        __syncthreads();
#pragma unroll
        for (int nn = 0; nn < 32; nn += 8) {
            int n = n0 + nn + ty;
            uchar4 p;
            p.x = (uint8_t)__nv_cvt_float_to_fp8(tile[tx*4+0][nn+ty] * FP8_SCALE, __NV_SATFINITE, __NV_E4M3);
            p.y = (uint8_t)__nv_cvt_float_to_fp8(tile[tx*4+1][nn+ty] * FP8_SCALE, __NV_SATFINITE, __NV_E4M3);
            p.z = (uint8_t)__nv_cvt_float_to_fp8(tile[tx*4+2][nn+ty] * FP8_SCALE, __NV_SATFINITE, __NV_E4M3);
            p.w = (uint8_t)__nv_cvt_float_to_fp8(tile[tx*4+3][nn+ty] * FP8_SCALE, __NV_SATFINITE, __NV_E4M3);
            *(uchar4*)&W8T[(long)n * DD2 + k0 + tx*4] = p;
        }
        return;
    }
    if (bid < NB_TR + NB_CV) {
        int b2 = bid - NB_TR;
        const float4* src;
        __nv_bfloat16* dst;
        int i;
        if (b2 < 1024)       { src = Wih_s; dst = Wih_d; i = b2*256 + tid; }
        else if (b2 < 2048)  { src = Whh_s; dst = Whh_d; i = (b2-1024)*256 + tid; }
        else if (b2 < 2560)  { src = Wd2_s; dst = Wd2_d; i = (b2-2048)*256 + tid; }
        else {
            int j = (b2-2560)*256 + tid;
            if (j < G4) bsum[j] = bih[j] + bhh[j];
            return;
        }
        float4 v = src[i];
        __nv_bfloat16 t[4];
        t[0] = __float2bfloat16(v.x);
        t[1] = __float2bfloat16(v.y);
        t[2] = __float2bfloat16(v.z);
        t[3] = __float2bfloat16(v.w);
        *(uint2*)&dst[4*i] = *(uint2*)t;
        return;
    }
    if (bid < NB_TR + NB_CV + NB_FT) {
        int b2 = bid - NB_TR - NB_CV;
        int b = b2 >> 1;
        int n = (b2 & 1) * 256 + tid;
        float* fs = &tile[0][0];
        fs[tid]       = features[b*EE + tid];
        fs[tid + 256] = features[b*EE + tid + 256];
        __syncthreads();
        float s = b_enc[n];
#pragma unroll 8
        for (int k = 0; k < EE; k++) s += fs[k] * W_enc[k*EE + n];
        X[(b*TT + 0)*EE + n] = __float2bfloat16(s);
        return;
    }
    int idx = (bid - NB_TR - NB_CV - NB_FT) * 256 + tid;
    int k = idx & (EE-1);
    int r = (idx >> 9) & 15;
    int b = idx >> 13;
    int cap = captions[b*TT + r];
    X[(b*TT + r + 1)*EE + k] = __float2bfloat16(emb[cap*EE + k]);
}

// ---------------- wmma GEMM (G gemm): Cf = A @ B^T + bias ----------------
template<int BM, int BN, int BK, int WM, int WN>
__global__ void __launch_bounds__(256)
gemm2(const __nv_bfloat16* __restrict__ A, const __nv_bfloat16* __restrict__ B,
      int M, int N, int K, const float* __restrict__ bias, float* __restrict__ Cf)
{
    constexpr int BKP = BK + 8;
    constexpr int ASZ = BM * BKP;
    constexpr int BSZ = BN * BKP;
    constexpr int WARPS_N = BN / WN;
    constexpr int FM = WM / 16;
    constexpr int FN = WN / 16;

    extern __shared__ __nv_bfloat16 dynsm[];
    __nv_bfloat16* Asb[2] = { dynsm, dynsm + ASZ };
    __nv_bfloat16* Bsb[2] = { dynsm + 2*ASZ, dynsm + 2*ASZ + BSZ };

    int tid  = threadIdx.x;
    int lane = tid & 31;
    int wid  = tid >> 5;
    int wr   = wid / WARPS_N;
    int wc   = wid % WARPS_N;
    int mBase = blockIdx.x * BM;
    int nBase = blockIdx.y * BN;

    wmma::fragment<wmma::accumulator, 16, 16, 16, float> acc[FM][FN];
#pragma unroll
    for (int i = 0; i < FM; i++)
#pragma unroll
        for (int j = 0; j < FN; j++)
            wmma::fill_fragment(acc[i][j], 0.0f);

    auto loadA = [&](int buf, int k0) {
        constexpr int CPR = BK / 8;
#pragma unroll
        for (int i = 0; i < BM*CPR/256; i++) {
            int cid = tid + i*256;
            int r = cid / CPR, cc = (cid % CPR) * 8;
            cpa16(&Asb[buf][r*BKP + cc], &A[(long)(mBase + r)*K + k0 + cc]);
        }
    };
    auto loadB = [&](int buf, int k0) {
        constexpr int CPR = BK / 8;
#pragma unroll
        for (int i = 0; i < BN*CPR/256; i++) {
            int cid = tid + i*256;
            int r = cid / CPR, cc = (cid % CPR) * 8;
            cpa16(&Bsb[buf][r*BKP + cc], &B[(long)(nBase + r)*K + k0 + cc]);
        }
    };

    loadA(0, 0); loadB(0, 0); cpa_commit();
    int KTn = K / BK;
    for (int kt = 0; kt < KTn; kt++) {
        int buf = kt & 1;
        cpa_wait<0>();
        __syncthreads();
        if (kt + 1 < KTn) { loadA(buf^1, (kt+1)*BK); loadB(buf^1, (kt+1)*BK); cpa_commit(); }
#pragma unroll
        for (int kk = 0; kk < BK; kk += 16) {
            wmma::fragment<wmma::matrix_a, 16, 16, 16, __nv_bfloat16, wmma::row_major> af[FM];
#pragma unroll
            for (int i = 0; i < FM; i++)
                wmma::load_matrix_sync(af[i], &Asb[buf][(wr*WM + i*16)*BKP + kk], BKP);
#pragma unroll
            for (int j = 0; j < FN; j++) {
                wmma::fragment<wmma::matrix_b, 16, 16, 16, __nv_bfloat16, wmma::col_major> bf;
                wmma::load_matrix_sync(bf, &Bsb[buf][(wc*WN + j*16)*BKP + kk], BKP);
#pragma unroll
                for (int i = 0; i < FM; i++)
                    wmma::mma_sync(acc[i][j], af[i], bf, acc[i][j]);
            }
        }
        __syncthreads();
    }

    float* myst = (float*)dynsm + wid * 256;
#pragma unroll
    for (int i = 0; i < FM; i++) {
#pragma unroll
        for (int j = 0; j < FN; j++) {
            wmma::store_matrix_sync(myst, acc[i][j], 16, wmma::mem_row_major);
            __syncwarp();
            int gr0 = mBase + wr*WM + i*16;
            int gc0 = nBase + wc*WN + j*16;
#pragma unroll
            for (int e = lane; e < 256; e += 32) {
                int rr = e >> 4, cc2 = e & 15;
                Cf[(long)(gr0 + rr)*N + (gc0 + cc2)] = myst[e] + bias[gc0 + cc2];
            }
            __syncwarp();
        }
    }
}

// ---------------- persistent LSTM + fused d2 GEMM (R14) ----------------
#define PW  520
#define PGP 132
#define D2_AP  72
#define D2_BP  136
#define GSM_OFF (128*PW*2 + 16*PW*2 + 16*PGP*4)     // 158208
__global__ void __launch_bounds__(256) lstm_persist(
    const __nv_bfloat16* __restrict__ Whh, const float* __restrict__ G,
    float* __restrict__ c, __nv_bfloat16* __restrict__ h, __nv_bfloat16* __restrict__ hs,
    const __nv_bfloat16* __restrict__ Wd2, const float* __restrict__ b_d2,
    uint8_t* __restrict__ out8)
{
    extern __shared__ char smraw[];
    __nv_bfloat16* Wsm = (__nv_bfloat16*)smraw;
    __nv_bfloat16* As  = (__nv_bfloat16*)(smraw + 128*PW*2);
    float*         Gst = (float*)(smraw + 128*PW*2 + 16*PW*2);
    float*         Gsm = (float*)(smraw + GSM_OFF);

    int tid = threadIdx.x, lane = tid & 31, wid = tid >> 5;
    int jc0 = (blockIdx.x >> 3) * 32;
    int b0  = (blockIdx.x & 7) * 16;

    auto loadG = [&](int buf, int t) {
#pragma unroll
        for (int i = 0; i < 2; i++) {
            int cid = tid + i*256;
            int row = cid >> 5, seg = (cid >> 3) & 3, off = (cid & 7) * 4;
            cpa16(&Gsm[buf*2048 + row*128 + seg*32 + off],
                  &G[((long)(b0 + row)*TT + t)*G4 + seg*512 + jc0 + off]);
        }
        cpa_commit();
    };

    loadG(0, 0);

#pragma unroll
    for (int i = 0; i < 32; i++) {
        int e = tid + i*256;
        int gr = e >> 6, cc = (e & 63) * 8;
        int gate = gr >> 5, r = gr & 31;
        *(uint4*)&Wsm[gr*PW + cc] = *(const uint4*)&Whh[(long)(gate*512 + jc0 + r)*512 + cc];
    }
    __syncthreads();

    auto gridbar = [&]() {
        __threadfence();
        __syncthreads();
        if (tid == 0) {
            unsigned old = *(volatile unsigned*)&g_gen;
            unsigned a = atomicAdd(&g_barcnt, 1);
            if (a == gridDim.x - 1) {
                g_barcnt = 0;
                __threadfence();
                atomicAdd(&g_gen, 1);
            } else {
                while (*(volatile unsigned*)&g_gen == old) { }
            }
        }
        __syncthreads();
        __threadfence();
    };

    for (int t = 0; t < TT; t++) {
        int gbuf = t & 1;

        if (t > 0) {
#pragma unroll
            for (int i = 0; i < 4; i++) {
                int e = tid + i*256;
                int r = e >> 6, cc = (e & 63) * 8;
                cpa16(&As[r*PW + cc], &h[(b0 + r)*HH + cc]);
            }
            cpa_commit();
        }
        cpa_wait<0>();
        __syncthreads();

        if (t > 0) {
            wmma::fragment<wmma::accumulator, 16, 16, 16, float> a0, a1;
            wmma::fill_fragment(a0, 0.0f);
            wmma::fill_fragment(a1, 0.0f);
#pragma unroll 4
            for (int kk = 0; kk < 256; kk += 16) {
                {
                    wmma::fragment<wmma::matrix_a, 16, 16, 16, __nv_bfloat16, wmma::row_major> af;
                    wmma::load_matrix_sync(af, &As[kk], PW);
                    wmma::fragment<wmma::matrix_b, 16, 16, 16, __nv_bfloat16, wmma::col_major> bf;
                    wmma::load_matrix_sync(bf, &Wsm[(wid*16)*PW + kk], PW);
                    wmma::mma_sync(a0, af, bf, a0);
                }
                {
                    wmma::fragment<wmma::matrix_a, 16, 16, 16, __nv_bfloat16, wmma::row_major> af;
                    wmma::load_matrix_sync(af, &As[kk + 256], PW);
                    wmma::fragment<wmma::matrix_b, 16, 16, 16, __nv_bfloat16, wmma::col_major> bf;
                    wmma::load_matrix_sync(bf, &Wsm[(wid*16)*PW + kk + 256], PW);
                    wmma::mma_sync(a1, af, bf, a1);
                }
            }
#pragma unroll
            for (int e2 = 0; e2 < a0.num_elements; e2++) a0.x[e2] += a1.x[e2];
            wmma::store_matrix_sync(&Gst[wid*16], a0, PGP, wmma::mem_row_major);
            __syncthreads();
        }

        if (t + 1 < TT) loadG(gbuf ^ 1, t + 1);

#pragma unroll
        for (int i = 0; i < 2; i++) {
            int e = i*256 + tid;
            int jr = e & 31, bl = e >> 5;
            int b = b0 + bl;
            int j = jc0 + jr;
            const float* gr2 = &Gsm[gbuf*2048 + bl*128];
            float s0 = 0.f, s1 = 0.f, s2 = 0.f, s3 = 0.f, cp = 0.f;
            if (t > 0) {
                s0 = Gst[bl*PGP + jr];
                s1 = Gst[bl*PGP + 32 + jr];
                s2 = Gst[bl*PGP + 64 + jr];
                s3 = Gst[bl*PGP + 96 + jr];
                cp = c[b*HH + j];
            }
            float gi = gr2[jr]        + s0;
            float gf = gr2[32 + jr]   + s1;
            float gg = gr2[64 + jr]   + s2;
            float go = gr2[96 + jr]   + s3;
            float i_ = 1.f / (1.f + __expf(-gi));
            float f_ = 1.f / (1.f + __expf(-gf));
            float o_ = 1.f / (1.f + __expf(-go));
            float g_ = tanhf(gg);
            float cn = f_*cp + i_*g_;
            float hn = o_*tanhf(cn);
            c[b*HH + j] = cn;
            __nv_bfloat16 hb = __float2bfloat16(hn);
            h[b*HH + j] = hb;
            hs[(long)(b*TT + t)*HH + j] = hb;
        }

        if (t < TT-1) gridbar();
    }

    gridbar();

    // ---------- fused d2 GEMM ----------
    __nv_bfloat16* As2 = (__nv_bfloat16*)smraw;
    __nv_bfloat16* Bs2 = (__nv_bfloat16*)(smraw + 2*128*D2_AP*2);
    float*         est = (float*)(smraw + 2*128*D2_AP*2 + 2*64*D2_BP*2);

    int wr2 = wid >> 1, wc2 = wid & 1;

    for (int tile = blockIdx.x; tile < 136; tile += gridDim.x) {
        int mBase = (tile % 17) * 128;
        int nBase = (tile / 17) * 128;
        __syncthreads();

        wmma::fragment<wmma::accumulator, 16, 16, 16, float> acc[2][4];
#pragma unroll
        for (int i = 0; i < 2; i++)
#pragma unroll
            for (int j = 0; j < 4; j++)
                wmma::fill_fragment(acc[i][j], 0.0f);

        auto loadA2 = [&](int buf, int k0) {
#pragma unroll
            for (int i = 0; i < 4; i++) {
                int cid = tid + i*256;
                int r = cid >> 3, cc = (cid & 7) * 8;
                cpa16(&As2[buf*128*D2_AP + r*D2_AP + cc], &hs[(long)(mBase + r)*HH + k0 + cc]);
            }
        };
        auto loadB2 = [&](int buf, int k0) {
#pragma unroll
            for (int i = 0; i < 4; i++) {
                int cid = tid + i*256;
                int r = cid >> 4, cc = (cid & 15) * 8;
                cpa16(&Bs2[buf*64*D2_BP + r*D2_BP + cc], &Wd2[(long)(k0 + r)*DD2 + nBase + cc]);
            }
        };

        loadA2(0, 0); loadB2(0, 0); cpa_commit();
        for (int kt = 0; kt < 8; kt++) {
            int buf = kt & 1;
            cpa_wait<0>();
            __syncthreads();
            if (kt + 1 < 8) { loadA2(buf^1, (kt+1)*64); loadB2(buf^1, (kt+1)*64); cpa_commit(); }
#pragma unroll
            for (int kk = 0; kk < 64; kk += 16) {
                wmma::fragment<wmma::matrix_a, 16, 16, 16, __nv_bfloat16, wmma::row_major> af[2];
#pragma unroll
                for (int i = 0; i < 2; i++)
                    wmma::load_matrix_sync(af[i], &As2[buf*128*D2_AP + (wr2*32 + i*16)*D2_AP + kk], D2_AP);
#pragma unroll
                for (int j = 0; j < 4; j++) {
                    wmma::fragment<wmma::matrix_b, 16, 16, 16, __nv_bfloat16, wmma::row_major> bf;
                    wmma::load_matrix_sync(bf, &Bs2[buf*64*D2_BP + kk*D2_BP + wc2*64 + j*16], D2_BP);
#pragma unroll
                    for (int i = 0; i < 2; i++)
                        wmma::mma_sync(acc[i][j], af[i], bf, acc[i][j]);
                }
            }
            __syncthreads();
        }

        float* myst = &est[wid * 256];
#pragma unroll
        for (int i = 0; i < 2; i++) {
#pragma unroll
            for (int j = 0; j < 4; j++) {
                wmma::store_matrix_sync(myst, acc[i][j], 16, wmma::mem_row_major);
                __syncwarp();
                int gr0 = mBase + wr2*32 + i*16;
                int gc0 = nBase + wc2*64 + j*16;
#pragma unroll
                for (int e = lane; e < 256; e += 32) {
                    int rr = e >> 4, cc2 = e & 15;
                    out8[(long)(gr0 + rr)*DD2 + (gc0 + cc2)] =
                        (uint8_t)__nv_cvt_float_to_fp8(
                            fmaxf(myst[e] + b_d2[gc0 + cc2], 0.f) * FP8_SCALE,
                            __NV_SATFINITE, __NV_E4M3);
                }
                __syncwarp();
            }
        }
    }
}

// ---------------- big fp8 GEMM: R10 mainloop + coalesced smem-staged epilogue ----------------
__global__ void __launch_bounds__(256, 2) gemm_big8(
    const uint8_t* __restrict__ A8, const uint8_t* __restrict__ B8,
    const float* __restrict__ bias, __nv_bfloat16* __restrict__ lgt, float* __restrict__ part)
{
    extern __shared__ uint8_t sm8[];
    __shared__ float pss[128][2];
    uint32_t sb = (uint32_t)__cvta_generic_to_shared(sm8);

    int tid  = threadIdx.x;
    int lane = tid & 31;
    int wid  = tid >> 5;
    int wr   = wid >> 1;
    int wc   = wid & 1;
    int mBase = blockIdx.x * MT2;
    int nBase = blockIdx.y * NT2;

    float acc[2][8][4];
#pragma unroll
    for (int f = 0; f < 2; f++)
#pragma unroll
        for (int j = 0; j < 8; j++)
#pragma unroll
            for (int e = 0; e < 4; e++) acc[f][j][e] = 0.f;

    const uint8_t* pA = A8 + (long)(mBase + (tid >> 3)) * DD2 + (tid & 7) * 16;
    const uint8_t* pB = B8 + (long)(nBase + (tid >> 3)) * DD2 + (tid & 7) * 16;
    const uint32_t dA = sb + sw128((uint32_t)((tid >> 3) * 128 + (tid & 7) * 16));
    const uint32_t dB = dA + MT2 * BKB;

    auto loadst = [&](int st, int k0) {
        uint32_t ab = dA + st * STG2;
        uint32_t bb = dB + st * STG2;
#pragma unroll
        for (int i = 0; i < 4; i++)
            cpa16s(ab + i * 4096, pA + k0 + i * 32 * DD2);
#pragma unroll
        for (int i = 0; i < 4; i++)
            cpa16s(bb + i * 4096, pB + k0 + i * 32 * DD2);
    };

    loadst(0, 0);       cpa_commit();
    loadst(1, BKB);     cpa_commit();

    int lrow = lane & 15;
    int lcol = (lane & 16) ? 16 : 0;
    uint32_t rowA[2], keyA[2];
#pragma unroll
    for (int f = 0; f < 2; f++) {
        int rr = wr * 32 + f * 16 + lrow;
        rowA[f] = (uint32_t)(rr * 128);
        keyA[f] = (uint32_t)((rr & 7) * 16);
    }
    uint32_t rowB[4], keyB[4];
#pragma unroll
    for (int g = 0; g < 4; g++) {
        int nn = wc * 64 + g * 16 + lrow;
        rowB[g] = (uint32_t)(MT2 * BKB + nn * 128);
        keyB[g] = (uint32_t)((nn & 7) * 16);
    }

    for (int kt = 0; kt < KIT; kt++) {
        int st = kt - (kt / 3) * 3;
        cpa_wait<1>();
        __syncthreads();
        if (kt + 2 < KIT) {
            int st2 = kt + 2;
            loadst(st2 - (st2 / 3) * 3, st2 * BKB);
        }
        cpa_commit();

        uint32_t stbase = sb + st * STG2;
#pragma unroll
        for (int s = 0; s < 4; s++) {
            uint32_t bytec = (uint32_t)(s * 32 + lcol);
            uint32_t a[2][4];
#pragma unroll
            for (int f = 0; f < 2; f++)
                ldsm_x4(a[f][0], a[f][1], a[f][2], a[f][3],
                        stbase + rowA[f] + (bytec ^ keyA[f]));
#pragma unroll
            for (int half = 0; half < 2; half++) {
                uint32_t b[4][2];
#pragma unroll
                for (int g = 0; g < 2; g++) {
                    uint32_t r0, r1, r2, r3;
                    ldsm_x4(r0, r1, r2, r3,
                            stbase + rowB[half*2 + g] + (bytec ^ keyB[half*2 + g]));
                    b[g*2][0] = r0; b[g*2+1][0] = r1;
                    b[g*2][1] = r2; b[g*2+1][1] = r3;
                }
#pragma unroll
                for (int f = 0; f < 2; f++)
#pragma unroll
                    for (int j = 0; j < 4; j++)
                        qmma(acc[f][half*4 + j], a[f], b[j]);
            }
        }
    }

    // ---- epilogue: stage bf16 logits in smem (stride EROW), then coalesced writes ----
    cpa_wait<0>();
    __syncthreads();          // all ldsm reads done -> stage buffers reusable

    float ps[4] = {0.f, 0.f, 0.f, 0.f};
    int rloc0 = wr * 32 + (lane >> 2);
#pragma unroll
    for (int f = 0; f < 2; f++) {
        int r0 = rloc0 + f * 16;
#pragma unroll
        for (int j = 0; j < 8; j++) {
            int colb = (wc * 64 + j * 8 + (lane & 3) * 2) * 2;   // byte offset in 256B row
            int col  = nBase + wc * 64 + j * 8 + (lane & 3) * 2;
            float2 bv = *(const float2*)&bias[col];
            float l0 = acc[f][j][0] * FP8_INV + bv.x;
            float l1 = acc[f][j][1] * FP8_INV + bv.y;
            float l2 = acc[f][j][2] * FP8_INV + bv.x;
            float l3 = acc[f][j][3] * FP8_INV + bv.y;
            ps[f*2]     += __expf(l0) + __expf(l1);
            ps[f*2 + 1] += __expf(l2) + __expf(l3);
            uint32_t p0 = bf2_to_u32(l0, l1);
            uint32_t p1 = bf2_to_u32(l2, l3);
            asm volatile("st.shared.b32 [%0], %1;" ::
                "r"(sb + (uint32_t)(r0 * EROW + colb)), "r"(p0) : "memory");
            asm volatile("st.shared.b32 [%0], %1;" ::
                "r"(sb + (uint32_t)((r0 + 8) * EROW + colb)), "r"(p1) : "memory");
        }
    }
#pragma unroll
    for (int k = 0; k < 4; k++) {
        ps[k] += __shfl_xor_sync(0xffffffffu, ps[k], 1);
        ps[k] += __shfl_xor_sync(0xffffffffu, ps[k], 2);
    }
    if ((lane & 3) == 0) {
#pragma unroll
        for (int f = 0; f < 2; f++) {
            pss[wr*32 + f*16 + (lane >> 2)][wc]     = ps[f*2];
            pss[wr*32 + f*16 + 8 + (lane >> 2)][wc] = ps[f*2 + 1];
        }
    }
    __syncthreads();

    // coalesced copy-out: 2048 chunks of 16B (8 bf16)
#pragma unroll
    for (int p = 0; p < 8; p++) {
        int e = p * 256 + tid;
        int row = e >> 4, ch = e & 15;
        uint32_t v0, v1, v2, v3;
        asm volatile("ld.shared.v4.b32 {%0,%1,%2,%3}, [%4];"
                     : "=r"(v0), "=r"(v1), "=r"(v2), "=r"(v3)
                     : "r"(sb + (uint32_t)(row * EROW + ch * 16)));
        uint4 v = make_uint4(v0, v1, v2, v3);
        *(uint4*)&lgt[(long)(mBase + row) * VV + nBase + ch * 8] = v;
    }

    if (tid < 128)
        part[(long)(mBase + tid) * NPART + blockIdx.y] = pss[tid][0] + pss[tid][1];
}

// ---------------- softmax: reduce partials, grid-stride exp+normalize ----------------
__global__ void partred_kernel(const float* __restrict__ part, float* __restrict__ rs) {
    __shared__ float red[256];
    int row = blockIdx.x, t = threadIdx.x;
    float s = (t < NPART) ? part[(long)row*NPART + t] : 0.f;
    red[t] = s;
    __syncthreads();
    for (int st = 128; st > 0; st >>= 1) {
        if (t < st) red[t] += red[t + st];
        __syncthreads();
    }
    if (t == 0) rs[row] = 1.f / red[0];
}

__global__ void normexp_kernel(const __nv_bfloat16* __restrict__ lgt,
                               const float* __restrict__ rs, float* __restrict__ out) {
    long idx = (long)blockIdx.x * blockDim.x + threadIdx.x;
    const long tot = (long)MM * VV / 8;
    if (idx >= tot) return;
    int row = (int)((idx * 8) / VV);
    float inv = rs[row];
    uint4 raw = ((const uint4*)lgt)[idx];
    __nv_bfloat162* bp = (__nv_bfloat162*)&raw;
    float4 o0, o1;
    float2 a0 = __bfloat1622float2(bp[0]);
    float2 a1 = __bfloat1622float2(bp[1]);
    float2 a2 = __bfloat1622float2(bp[2]);
    float2 a3 = __bfloat1622float2(bp[3]);
    o0.x = __expf(a0.x) * inv; o0.y = __expf(a0.y) * inv;
    o0.z = __expf(a1.x) * inv; o0.w = __expf(a1.y) * inv;
    o1.x = __expf(a2.x) * inv; o1.y = __expf(a2.y) * inv;
    o1.z = __expf(a3.x) * inv; o1.w = __expf(a3.y) * inv;
    ((float4*)out)[idx*2]     = o0;
    ((float4*)out)[idx*2 + 1] = o1;
}

// ---------------- host launcher ----------------
extern "C" void kernel_launch(void* const* d_in, const int* in_sizes, int n_in,
                              void* d_out, int out_size) {
    const float* features = (const float*)d_in[0];
    const int*   captions = (const int*)  d_in[1];
    const float* W_enc    = (const float*)d_in[2];
    const float* b_enc    = (const float*)d_in[3];
    const float* emb      = (const float*)d_in[4];
    const float* W_ih     = (const float*)d_in[5];
    const float* b_ih     = (const float*)d_in[6];
    const float* W_hh     = (const float*)d_in[7];
    const float* b_hh     = (const float*)d_in[8];
    const float* W_d2     = (const float*)d_in[9];
    const float* b_d2     = (const float*)d_in[10];
    const float* W_last   = (const float*)d_in[11];
    const float* b_last   = (const float*)d_in[12];
    float* out = (float*)d_out;

    void *pX, *pG, *ph, *pc, *phs, *pout8, *pWih, *pWhh, *pWd2, *pW8T, *plgt, *pbsum, *prs, *ppart;
    cudaGetSymbolAddress(&pX, g_X);
    cudaGetSymbolAddress(&pG, g_G);
    cudaGetSymbolAddress(&ph, g_h);
    cudaGetSymbolAddress(&pc, g_c);
    cudaGetSymbolAddress(&phs, g_hs);
    cudaGetSymbolAddress(&pout8, g_out8);
    cudaGetSymbolAddress(&pWih, g_Wih);
    cudaGetSymbolAddress(&pWhh, g_Whh);
    cudaGetSymbolAddress(&pWd2, g_Wd2);
    cudaGetSymbolAddress(&pW8T, g_W8T);
    cudaGetSymbolAddress(&plgt, g_lgt);
    cudaGetSymbolAddress(&pbsum, g_bsum);
    cudaGetSymbolAddress(&prs, g_rs);
    cudaGetSymbolAddress(&ppart, g_part);

    __nv_bfloat16* X     = (__nv_bfloat16*)pX;
    float*         G     = (float*)pG;
    __nv_bfloat16* h     = (__nv_bfloat16*)ph;
    float*         c     = (float*)pc;
    __nv_bfloat16* hs    = (__nv_bfloat16*)phs;
    uint8_t*       out8  = (uint8_t*)pout8;
    __nv_bfloat16* Wih   = (__nv_bfloat16*)pWih;
    __nv_bfloat16* Whh   = (__nv_bfloat16*)pWhh;
    __nv_bfloat16* Wd2   = (__nv_bfloat16*)pWd2;
    uint8_t*       W8T   = (uint8_t*)pW8T;
    __nv_bfloat16* lgt   = (__nv_bfloat16*)plgt;
    float*         bsum  = (float*)pbsum;
    float*         rs    = (float*)prs;
    float*         part  = (float*)ppart;

    const int SMEM_T = 2*(128*40 + 256*40)*2;
    const int SMEM_P = GSM_OFF + 2*16*128*4;    // 174592
    const int SMEM_B8 = NSTG * STG2;            // 98304 (>= 128*EROW=34816 for epilogue)
    cudaFuncSetAttribute(gemm2<128,256,32,64,64>,
                         cudaFuncAttributeMaxDynamicSharedMemorySize, SMEM_T);
    cudaFuncSetAttribute(lstm_persist,
                         cudaFuncAttributeMaxDynamicSharedMemorySize, SMEM_P);
    cudaFuncSetAttribute(gemm_big8,
                         cudaFuncAttributeMaxDynamicSharedMemorySize, SMEM_B8);

    // launch 1: all prologue work fused
    prep<<<NB_TR + NB_CV + NB_FT + NB_GA, 256>>>(
        W_last, W8T,
        (const float4*)W_ih, Wih, (const float4*)W_hh, Whh, (const float4*)W_d2, Wd2,
        b_ih, b_hh, bsum,
        features, W_enc, b_enc, captions, emb, X);

    // launch 2: G = X @ W_ih^T + (b_ih + b_hh)
    gemm2<128,256,32,64,64>
        <<<dim3(MM/128, G4/256), 256, SMEM_T>>>(X, Wih, MM, G4, EE, bsum, G);

    // launch 3: persistent LSTM + fused d2 GEMM -> out8
    lstm_persist<<<128, 256, SMEM_P>>>(Whh, G, c, h, hs, Wd2, b_d2, out8);

    // launch 4: big fp8 GEMM (profiled slot)
    gemm_big8<<<dim3(MM/MT2, VV/NT2), 256, SMEM_B8>>>(out8, W8T, b_last, lgt, part);

    // softmax
    partred_kernel<<<MM, 256>>>(part, rs);
    normexp_kernel<<<(int)(((long)MM*VV/8 + 255)/256), 256>>>(lgt, rs, out);
}